// round 13
// baseline (speedup 1.0000x reference)
#include <cuda_runtime.h>
#include <cuda_bf16.h>

#define NNODES 50000
#define NEDGES 800000
#define ETOT   (NNODES + NEDGES)
#define NGRAPH 16
#define CAP    128

// packed-weight offsets (unsigned = bf16x2 along K)
#define OFF_ENC 0        // 16*64   = 1024
#define OFF_W1  1024     // 32*256  = 8192
#define OFF_W2  9216     // 128*256 = 32768
#define OFF_W3  41984    // 128*64  = 8192
#define WP_TOT  50176

// ---------------- scratch (device globals; allocation-free rule) ----------------
__device__ __align__(128) __nv_bfloat16 g_h0[NNODES * 64];      // encoder output (bf16)
__device__ __align__(128) __nv_bfloat16 g_bufA[NNODES * 256];   // conv outputs (bf16)
__device__ __align__(128) __nv_bfloat16 g_bufB[NNODES * 256];   // h @ W (bf16, per-conv)
__device__ __align__(128) float g_h3[NNODES * 64];              // conv3 output (fp32)
__device__ __align__(128) unsigned g_Wp[WP_TOT];                // packed bf16 weights
__device__ float g_asA[3 * NNODES * 4];
__device__ float g_adA[3 * NNODES * 4];
__device__ int   g_deg[NNODES];
__device__ int   g_fill[NNODES];
__device__ int   g_rowptr[NNODES + 1];
__device__ int   g_csrc[ETOT];
__device__ float g_pool[NGRAPH * 64 + NGRAPH];  // sums then counts

// ---------------- side stream for CSR/GEMM overlap ----------------
struct StreamBundle {
    cudaStream_t s2;
    cudaEvent_t ev_fork, ev_join;
    StreamBundle() {
        cudaStreamCreateWithFlags(&s2, cudaStreamNonBlocking);
        cudaEventCreateWithFlags(&ev_fork, cudaEventDisableTiming);
        cudaEventCreateWithFlags(&ev_join, cudaEventDisableTiming);
    }
};
static StreamBundle g_sb;

__device__ __forceinline__ unsigned pack_bf2(float x, float y) {
    __nv_bfloat162 t = __floats2bfloat162_rn(x, y);
    return *reinterpret_cast<unsigned*>(&t);
}

// ---------------- setup (split: CSR zeros on side stream, pool zeros on main) ----
__global__ void zero_csr_kernel() {
    int i = blockIdx.x * blockDim.x + threadIdx.x;
    if (i < NNODES) { g_deg[i] = 0; g_fill[i] = 0; }
}
__global__ void zero_pool_kernel() {
    int i = blockIdx.x * blockDim.x + threadIdx.x;
    if (i < NGRAPH * 64 + NGRAPH) g_pool[i] = 0.f;
}

// ---------------- pack all weights to bf16 K-pairs, [n][kp] layout ----------------
__global__ void packW_all_kernel(const float* __restrict__ Wenc,
                                 const float* __restrict__ W1,
                                 const float* __restrict__ W2,
                                 const float* __restrict__ W3) {
    int idx = blockIdx.x * blockDim.x + threadIdx.x;
    if (idx >= WP_TOT) return;
    const float* W; int Kd2, Nd; unsigned* dst; int local;
    if (idx < OFF_W1)       { W = Wenc; Kd2 = 16;  Nd = 64;  dst = g_Wp + OFF_ENC; local = idx - OFF_ENC; }
    else if (idx < OFF_W2)  { W = W1;   Kd2 = 32;  Nd = 256; dst = g_Wp + OFF_W1;  local = idx - OFF_W1; }
    else if (idx < OFF_W3)  { W = W2;   Kd2 = 128; Nd = 256; dst = g_Wp + OFF_W2;  local = idx - OFF_W2; }
    else                    { W = W3;   Kd2 = 128; Nd = 64;  dst = g_Wp + OFF_W3;  local = idx - OFF_W3; }
    int n = local / Kd2, kp = local % Kd2;
    dst[local] = pack_bf2(W[(size_t)(2 * kp) * Nd + n], W[(size_t)(2 * kp + 1) * Nd + n]);
}

// ---------------- CSR build ----------------
__global__ void deg_kernel(const int* __restrict__ ei) {
    int e = blockIdx.x * blockDim.x + threadIdx.x;
    if (e >= ETOT) return;
    int dst = (e < NEDGES) ? ei[NEDGES + e] : (e - NEDGES);
    atomicAdd(&g_deg[dst], 1);
}

// smem-staged single-block scan: coalesced global IO, chunk-sequential work in smem
__global__ void scan_kernel() {
    extern __shared__ int sdeg[];   // NNODES ints (200 KB)
    __shared__ int warp_sums[32];
    int t = threadIdx.x;
    for (int i = t; i < NNODES; i += 1024) sdeg[i] = g_deg[i];
    __syncthreads();

    const int PER = (NNODES + 1023) / 1024;  // 49
    int start = t * PER;
    int end = min(start + PER, NNODES);
    int local = 0;
    for (int i = start; i < end; i++) local += sdeg[i];

    int lane = t & 31, w = t >> 5;
    int v = local;
#pragma unroll
    for (int off = 1; off < 32; off <<= 1) {
        int n = __shfl_up_sync(0xffffffffu, v, off);
        if (lane >= off) v += n;
    }
    if (lane == 31) warp_sums[w] = v;
    __syncthreads();
    if (w == 0) {
        int s = warp_sums[lane];
#pragma unroll
        for (int off = 1; off < 32; off <<= 1) {
            int n = __shfl_up_sync(0xffffffffu, s, off);
            if (lane >= off) s += n;
        }
        warp_sums[lane] = s;
    }
    __syncthreads();
    int excl = v - local + (w > 0 ? warp_sums[w - 1] : 0);

    int run = excl;
    for (int i = start; i < end; i++) { int d = sdeg[i]; sdeg[i] = run; run += d; }
    if (end == NNODES && start < NNODES) g_rowptr[NNODES] = run;
    __syncthreads();
    for (int i = t; i < NNODES; i += 1024) g_rowptr[i] = sdeg[i];
}

__global__ void fill_kernel(const int* __restrict__ ei) {
    int e = blockIdx.x * blockDim.x + threadIdx.x;
    if (e >= ETOT) return;
    int src, dst;
    if (e < NEDGES) { src = ei[e]; dst = ei[NEDGES + e]; }
    else            { src = dst = e - NEDGES; }
    int pos = g_rowptr[dst] + atomicAdd(&g_fill[dst], 1);
    g_csrc[pos] = src;
}

// ---------------- bf16 tensor-core GEMM (+ fused attention epilogue) ----------------
#define BM 128
#define BN 64
#define BK 32
#define AST 20
#define BST 20

__device__ __forceinline__ void mma_bf16(float* d, const unsigned* a, const unsigned* b) {
    asm volatile(
        "mma.sync.aligned.m16n8k16.row.col.f32.bf16.bf16.f32 "
        "{%0,%1,%2,%3}, {%4,%5,%6,%7}, {%8,%9}, {%0,%1,%2,%3};"
        : "+f"(d[0]), "+f"(d[1]), "+f"(d[2]), "+f"(d[3])
        : "r"(a[0]), "r"(a[1]), "r"(a[2]), "r"(a[3]), "r"(b[0]), "r"(b[1]));
}

// A_BF16: A rows packed bf16; else fp32. B: pre-packed bf16 K-pairs [n][kp].
// OUT_BF16: C is bf16 packed rows. FUSE_ATTN: a_s/a_d direct store (head = bn>>6).
template <bool ADD_BIAS, bool OUT_BF16, bool FUSE_ATTN, bool A_BF16>
__global__ __launch_bounds__(256) void gemm_kernel(
    const void* __restrict__ Av, const unsigned* __restrict__ Bp,
    const float* __restrict__ bias, void* __restrict__ Cv,
    int M, int Kd, int Nd,
    const float* __restrict__ atts, const float* __restrict__ attd,
    float* __restrict__ as_out, float* __restrict__ ad_out, int hstride)
{
    __shared__ unsigned As[BM * AST];
    __shared__ unsigned Bs[BN * BST];

    int t = threadIdx.x;
    int bm = blockIdx.y * BM, bn = blockIdx.x * BN;
    int wid = t >> 5, lane = t & 31;
    int wm = (wid >> 1) * 32, wn = (wid & 1) * 32;
    int r0 = lane >> 2, p = lane & 3;
    int Kd2 = Kd >> 1;

    float acc[2][4][4] = {};
    float4 arf[4];
    uint4  arb[2];
    unsigned br[4];

    auto loadB = [&](int k02) {
#pragma unroll
        for (int i = 0; i < 4; i++) {
            int task = t + i * 256;
            int kp = task & 15, n = task >> 4;
            br[i] = Bp[(size_t)(bn + n) * Kd2 + k02 + kp];
        }
    };
    auto storeB = [&]() {
#pragma unroll
        for (int i = 0; i < 4; i++) {
            int task = t + i * 256;
            int kp = task & 15, n = task >> 4;
            Bs[n * BST + kp] = br[i];
        }
    };

    if (A_BF16) {
        const __nv_bfloat16* A = (const __nv_bfloat16*)Av;
#pragma unroll
        for (int i = 0; i < 2; i++) {
            int idx = t + i * 256;
            int row = idx >> 2, c4 = idx & 3;
            int grow = bm + row;
            arb[i] = (grow < M) ? *reinterpret_cast<const uint4*>(A + (size_t)grow * Kd + c4 * 8)
                                : make_uint4(0u, 0u, 0u, 0u);
        }
    } else {
        const float* A = (const float*)Av;
#pragma unroll
        for (int i = 0; i < 4; i++) {
            int f4 = t + i * 256;
            int row = f4 >> 3, c4 = f4 & 7;
            int grow = bm + row;
            arf[i] = (grow < M) ? *reinterpret_cast<const float4*>(A + (size_t)grow * Kd + c4 * 4)
                                : make_float4(0.f, 0.f, 0.f, 0.f);
        }
    }
    loadB(0);
    if (A_BF16) {
#pragma unroll
        for (int i = 0; i < 2; i++) {
            int idx = t + i * 256;
            int row = idx >> 2, c4 = idx & 3;
            unsigned* dst = &As[row * AST + c4 * 4];
            dst[0] = arb[i].x; dst[1] = arb[i].y; dst[2] = arb[i].z; dst[3] = arb[i].w;
        }
    } else {
#pragma unroll
        for (int i = 0; i < 4; i++) {
            int f4 = t + i * 256;
            int row = f4 >> 3, c4 = f4 & 7;
            As[row * AST + c4 * 2]     = pack_bf2(arf[i].x, arf[i].y);
            As[row * AST + c4 * 2 + 1] = pack_bf2(arf[i].z, arf[i].w);
        }
    }
    storeB();
    __syncthreads();

    int niter = Kd / BK;
    for (int it = 0; it < niter; it++) {
        if (it + 1 < niter) {
            int k0 = (it + 1) * BK;
            if (A_BF16) {
                const __nv_bfloat16* A = (const __nv_bfloat16*)Av;
#pragma unroll
                for (int i = 0; i < 2; i++) {
                    int idx = t + i * 256;
                    int row = idx >> 2, c4 = idx & 3;
                    int grow = bm + row;
                    arb[i] = (grow < M)
                           ? *reinterpret_cast<const uint4*>(A + (size_t)grow * Kd + k0 + c4 * 8)
                           : make_uint4(0u, 0u, 0u, 0u);
                }
            } else {
                const float* A = (const float*)Av;
#pragma unroll
                for (int i = 0; i < 4; i++) {
                    int f4 = t + i * 256;
                    int row = f4 >> 3, c4 = f4 & 7;
                    int grow = bm + row;
                    arf[i] = (grow < M)
                           ? *reinterpret_cast<const float4*>(A + (size_t)grow * Kd + k0 + c4 * 4)
                           : make_float4(0.f, 0.f, 0.f, 0.f);
                }
            }
            loadB((it + 1) * (BK / 2));
        }
#pragma unroll
        for (int ks = 0; ks < 2; ks++) {
            int kb = ks * 8;
            unsigned ah[2][4];
#pragma unroll
            for (int mt = 0; mt < 2; mt++) {
                int base = (wm + mt * 16 + r0) * AST + kb + p;
                ah[mt][0] = As[base];
                ah[mt][1] = As[base + 8 * AST];
                ah[mt][2] = As[base + 4];
                ah[mt][3] = As[base + 8 * AST + 4];
            }
            unsigned bh[4][2];
#pragma unroll
            for (int nt = 0; nt < 4; nt++) {
                int base = (wn + nt * 8 + r0) * BST + kb + p;
                bh[nt][0] = Bs[base];
                bh[nt][1] = Bs[base + 4];
            }
#pragma unroll
            for (int mt = 0; mt < 2; mt++)
#pragma unroll
                for (int nt = 0; nt < 4; nt++)
                    mma_bf16(acc[mt][nt], ah[mt], bh[nt]);
        }
        __syncthreads();
        if (it + 1 < niter) {
            if (A_BF16) {
#pragma unroll
                for (int i = 0; i < 2; i++) {
                    int idx = t + i * 256;
                    int row = idx >> 2, c4 = idx & 3;
                    unsigned* dst = &As[row * AST + c4 * 4];
                    dst[0] = arb[i].x; dst[1] = arb[i].y; dst[2] = arb[i].z; dst[3] = arb[i].w;
                }
            } else {
#pragma unroll
                for (int i = 0; i < 4; i++) {
                    int f4 = t + i * 256;
                    int row = f4 >> 3, c4 = f4 & 7;
                    As[row * AST + c4 * 2]     = pack_bf2(arf[i].x, arf[i].y);
                    As[row * AST + c4 * 2 + 1] = pack_bf2(arf[i].z, arf[i].w);
                }
            }
            storeB();
            __syncthreads();
        }
    }

    // epilogue (+ optional fused attention partials)
    float sA[2] = {0.f, 0.f}, dA[2] = {0.f, 0.f};
    float sB[2] = {0.f, 0.f}, dB[2] = {0.f, 0.f};
    const float* attsh = FUSE_ATTN ? atts + (bn >> 6) * 64 : nullptr;
    const float* attdh = FUSE_ATTN ? attd + (bn >> 6) * 64 : nullptr;
#pragma unroll
    for (int mt = 0; mt < 2; mt++) {
#pragma unroll
        for (int nt = 0; nt < 4; nt++) {
            int grow0 = bm + wm + mt * 16 + r0;
            int gcol = bn + wn + nt * 8 + 2 * p;
            float b0v = 0.f, b1v = 0.f;
            if (ADD_BIAS) { b0v = bias[gcol]; b1v = bias[gcol + 1]; }
            float* c = acc[mt][nt];
            if (FUSE_ATTN) {
                int cih = wn + nt * 8 + 2 * p;
                float a0 = attsh[cih], a1 = attsh[cih + 1];
                float t0 = attdh[cih], t1 = attdh[cih + 1];
                sA[mt] += c[0] * a0 + c[1] * a1;
                dA[mt] += c[0] * t0 + c[1] * t1;
                sB[mt] += c[2] * a0 + c[3] * a1;
                dB[mt] += c[2] * t0 + c[3] * t1;
            }
            if (OUT_BF16) {
                __nv_bfloat162* Cb = (__nv_bfloat162*)Cv;
                if (grow0 < M)
                    Cb[((size_t)grow0 * Nd + gcol) >> 1] = __floats2bfloat162_rn(c[0] + b0v, c[1] + b1v);
                if (grow0 + 8 < M)
                    Cb[((size_t)(grow0 + 8) * Nd + gcol) >> 1] = __floats2bfloat162_rn(c[2] + b0v, c[3] + b1v);
            } else {
                float* C = (float*)Cv;
                if (grow0 < M) {
                    C[(size_t)grow0 * Nd + gcol]     = c[0] + b0v;
                    C[(size_t)grow0 * Nd + gcol + 1] = c[1] + b1v;
                }
                if (grow0 + 8 < M) {
                    C[(size_t)(grow0 + 8) * Nd + gcol]     = c[2] + b0v;
                    C[(size_t)(grow0 + 8) * Nd + gcol + 1] = c[3] + b1v;
                }
            }
        }
    }
    if (FUSE_ATTN) {
        int head = bn >> 6;
#pragma unroll
        for (int mt = 0; mt < 2; mt++) {
            sA[mt] += __shfl_xor_sync(0xffffffffu, sA[mt], 1); sA[mt] += __shfl_xor_sync(0xffffffffu, sA[mt], 2);
            dA[mt] += __shfl_xor_sync(0xffffffffu, dA[mt], 1); dA[mt] += __shfl_xor_sync(0xffffffffu, dA[mt], 2);
            sB[mt] += __shfl_xor_sync(0xffffffffu, sB[mt], 1); sB[mt] += __shfl_xor_sync(0xffffffffu, sB[mt], 2);
            dB[mt] += __shfl_xor_sync(0xffffffffu, dB[mt], 1); dB[mt] += __shfl_xor_sync(0xffffffffu, dB[mt], 2);
        }
        float* s_rs = reinterpret_cast<float*>(As);   // [BM]
        float* s_rd = s_rs + BM;                      // [BM]
        __syncthreads();
        if ((wid & 1) == 0 && p == 0) {
#pragma unroll
            for (int mt = 0; mt < 2; mt++) {
                int r = wm + mt * 16 + r0;
                s_rs[r] = sA[mt];     s_rd[r] = dA[mt];
                s_rs[r + 8] = sB[mt]; s_rd[r + 8] = dB[mt];
            }
        }
        __syncthreads();
        if ((wid & 1) == 1 && p == 0) {
#pragma unroll
            for (int mt = 0; mt < 2; mt++) {
                int r = wm + mt * 16 + r0;
                int gr = bm + r;
                if (gr < M) {
                    as_out[(size_t)gr * hstride + head] = s_rs[r] + sA[mt];
                    ad_out[(size_t)gr * hstride + head] = s_rd[r] + dA[mt];
                }
                if (gr + 8 < M) {
                    as_out[(size_t)(gr + 8) * hstride + head] = s_rs[r + 8] + sB[mt];
                    ad_out[(size_t)(gr + 8) * hstride + head] = s_rd[r + 8] + dB[mt];
                }
            }
        }
    }
}

// ---------------- 4-head aggregation: 4 nodes per 256-thread block ----------------
// Groups of 64 threads per node; syncs are hoisted to uniform points so
// divergent small/large-degree paths never enclose __syncthreads.
__global__ __launch_bounds__(256) void agg4_kernel(
    const __nv_bfloat16* __restrict__ hw,
    const float* __restrict__ asv, const float* __restrict__ adv,
    const float* __restrict__ bias, __nv_bfloat16* __restrict__ out)
{
    int gg = threadIdx.x >> 6;       // group 0..3
    int tid = threadIdx.x & 63;      // thread within group
    int node = blockIdx.x * 4 + gg;  // NNODES divisible by 4
    int start = g_rowptr[node];
    int deg = g_rowptr[node + 1] - start;
    bool small = (deg <= CAP);

    __shared__ int   s_src[4][CAP];
    __shared__ float s_e[4][4][CAP];
    __shared__ float s_scale[4][4], s_m[4][4], s_adv[4][4];

    int w = tid >> 5, lane = tid & 31;
    int h3 = tid >> 4;
    float4 acc = make_float4(0.f, 0.f, 0.f, 0.f);
    const uint2* hw8 = reinterpret_cast<const uint2*>(hw);

    // stage 1: cache src indices (small path)
    if (small) {
        for (int i = tid; i < deg; i += 64) s_src[gg][i] = g_csrc[start + i];
    }
    __syncthreads();

    // stage 2: softmax stats per head (warp w handles heads w, w+2)
    for (int h = w; h < 4; h += 2) {
        float adh = adv[node * 4 + h];
        float mx = -1e30f;
        if (small) {
            for (int i = lane; i < deg; i += 32) {
                float e = asv[s_src[gg][i] * 4 + h] + adh;
                e = e >= 0.f ? e : 0.2f * e;
                s_e[gg][h][i] = e;
                mx = fmaxf(mx, e);
            }
        } else {
            for (int i = lane; i < deg; i += 32) {
                float e = asv[g_csrc[start + i] * 4 + h] + adh;
                e = e >= 0.f ? e : 0.2f * e;
                mx = fmaxf(mx, e);
            }
        }
#pragma unroll
        for (int o = 16; o; o >>= 1) mx = fmaxf(mx, __shfl_xor_sync(0xffffffffu, mx, o));
        float den = 0.f;
        if (small) {
            for (int i = lane; i < deg; i += 32) {
                float ex = __expf(s_e[gg][h][i] - mx);
                s_e[gg][h][i] = ex;
                den += ex;
            }
        } else {
            for (int i = lane; i < deg; i += 32) {
                float e = asv[g_csrc[start + i] * 4 + h] + adh;
                e = e >= 0.f ? e : 0.2f * e;
                den += __expf(e - mx);
            }
        }
#pragma unroll
        for (int o = 16; o; o >>= 1) den += __shfl_xor_sync(0xffffffffu, den, o);
        if (lane == 0) {
            s_scale[gg][h] = 1.f / (den + 1e-16f);
            s_m[gg][h] = mx;
            s_adv[gg][h] = adh;
        }
    }
    __syncthreads();

    // stage 3: weighted gather
    if (small) {
        const float* eh = s_e[gg][h3];
        const int* srcp = s_src[gg];
        int i = 0;
        for (; i + 4 <= deg; i += 4) {
            int s0 = srcp[i], s1 = srcp[i + 1], s2 = srcp[i + 2], s3 = srcp[i + 3];
            float e0 = eh[i], e1 = eh[i + 1], e2 = eh[i + 2], e3 = eh[i + 3];
            uint2 u0 = hw8[(size_t)s0 * 64 + tid];
            uint2 u1 = hw8[(size_t)s1 * 64 + tid];
            uint2 u2 = hw8[(size_t)s2 * 64 + tid];
            uint2 u3 = hw8[(size_t)s3 * 64 + tid];
            float2 a0 = __bfloat1622float2(*reinterpret_cast<__nv_bfloat162*>(&u0.x));
            float2 b0 = __bfloat1622float2(*reinterpret_cast<__nv_bfloat162*>(&u0.y));
            float2 a1 = __bfloat1622float2(*reinterpret_cast<__nv_bfloat162*>(&u1.x));
            float2 b1 = __bfloat1622float2(*reinterpret_cast<__nv_bfloat162*>(&u1.y));
            float2 a2 = __bfloat1622float2(*reinterpret_cast<__nv_bfloat162*>(&u2.x));
            float2 b2 = __bfloat1622float2(*reinterpret_cast<__nv_bfloat162*>(&u2.y));
            float2 a3 = __bfloat1622float2(*reinterpret_cast<__nv_bfloat162*>(&u3.x));
            float2 b3 = __bfloat1622float2(*reinterpret_cast<__nv_bfloat162*>(&u3.y));
            acc.x += e0 * a0.x + e1 * a1.x + e2 * a2.x + e3 * a3.x;
            acc.y += e0 * a0.y + e1 * a1.y + e2 * a2.y + e3 * a3.y;
            acc.z += e0 * b0.x + e1 * b1.x + e2 * b2.x + e3 * b3.x;
            acc.w += e0 * b0.y + e1 * b1.y + e2 * b2.y + e3 * b3.y;
        }
        for (; i < deg; i++) {
            float e0 = eh[i];
            uint2 u0 = hw8[(size_t)srcp[i] * 64 + tid];
            float2 a0 = __bfloat1622float2(*reinterpret_cast<__nv_bfloat162*>(&u0.x));
            float2 b0 = __bfloat1622float2(*reinterpret_cast<__nv_bfloat162*>(&u0.y));
            acc.x += e0 * a0.x; acc.y += e0 * a0.y;
            acc.z += e0 * b0.x; acc.w += e0 * b0.y;
        }
    } else {
        float mxh = s_m[gg][h3], adh = s_adv[gg][h3];
        for (int i = 0; i < deg; i++) {
            int s = g_csrc[start + i];
            float e = asv[s * 4 + h3] + adh;
            e = e >= 0.f ? e : 0.2f * e;
            float ex = __expf(e - mxh);
            uint2 u0 = hw8[(size_t)s * 64 + tid];
            float2 a0 = __bfloat1622float2(*reinterpret_cast<__nv_bfloat162*>(&u0.x));
            float2 b0 = __bfloat1622float2(*reinterpret_cast<__nv_bfloat162*>(&u0.y));
            acc.x += ex * a0.x; acc.y += ex * a0.y;
            acc.z += ex * b0.x; acc.w += ex * b0.y;
        }
    }

    float sc = s_scale[gg][h3];
    float4 b = reinterpret_cast<const float4*>(bias)[tid];
    acc.x = acc.x * sc + b.x;
    acc.y = acc.y * sc + b.y;
    acc.z = acc.z * sc + b.z;
    acc.w = acc.w * sc + b.w;
    acc.x = acc.x > 0.f ? acc.x : (__expf(acc.x) - 1.f);
    acc.y = acc.y > 0.f ? acc.y : (__expf(acc.y) - 1.f);
    acc.z = acc.z > 0.f ? acc.z : (__expf(acc.z) - 1.f);
    acc.w = acc.w > 0.f ? acc.w : (__expf(acc.w) - 1.f);
    __nv_bfloat162 p0 = __floats2bfloat162_rn(acc.x, acc.y);
    __nv_bfloat162 p1 = __floats2bfloat162_rn(acc.z, acc.w);
    uint2 o;
    o.x = *reinterpret_cast<unsigned*>(&p0);
    o.y = *reinterpret_cast<unsigned*>(&p1);
    reinterpret_cast<uint2*>(out)[(size_t)node * 64 + tid] = o;
}

// ---------------- 1-head aggregation: warp per node, bf162 gather, fp32 out ----------------
__global__ __launch_bounds__(64) void agg1_kernel(
    const __nv_bfloat16* __restrict__ hw,
    const float* __restrict__ asv, const float* __restrict__ adv,
    const float* __restrict__ bias, float* __restrict__ out)
{
    __shared__ int   s_src[2][CAP];
    __shared__ float s_e[2][CAP];
    int w = threadIdx.x >> 5, lane = threadIdx.x & 31;
    int node = blockIdx.x * 2 + w;
    if (node >= NNODES) return;
    int start = g_rowptr[node];
    int deg = g_rowptr[node + 1] - start;
    float adh = adv[node];

    float acc_x = 0.f, acc_y = 0.f;
    float den;
    const __nv_bfloat162* hw2 = reinterpret_cast<const __nv_bfloat162*>(hw);

    if (deg <= CAP) {
        float mx = -1e30f;
        for (int i = lane; i < deg; i += 32) {
            int s = g_csrc[start + i];
            s_src[w][i] = s;
            float e = asv[s] + adh;
            e = e >= 0.f ? e : 0.2f * e;
            s_e[w][i] = e;
            mx = fmaxf(mx, e);
        }
#pragma unroll
        for (int o = 16; o; o >>= 1) mx = fmaxf(mx, __shfl_xor_sync(0xffffffffu, mx, o));
        __syncwarp();
        den = 0.f;
        for (int i = lane; i < deg; i += 32) {
            float ex = __expf(s_e[w][i] - mx);
            s_e[w][i] = ex;
            den += ex;
        }
#pragma unroll
        for (int o = 16; o; o >>= 1) den += __shfl_xor_sync(0xffffffffu, den, o);
        __syncwarp();
        int i = 0;
        for (; i + 4 <= deg; i += 4) {
            int s0 = s_src[w][i], s1 = s_src[w][i + 1], s2 = s_src[w][i + 2], s3 = s_src[w][i + 3];
            float e0 = s_e[w][i], e1 = s_e[w][i + 1], e2 = s_e[w][i + 2], e3 = s_e[w][i + 3];
            float2 v0 = __bfloat1622float2(hw2[(size_t)s0 * 32 + lane]);
            float2 v1 = __bfloat1622float2(hw2[(size_t)s1 * 32 + lane]);
            float2 v2 = __bfloat1622float2(hw2[(size_t)s2 * 32 + lane]);
            float2 v3 = __bfloat1622float2(hw2[(size_t)s3 * 32 + lane]);
            acc_x += e0 * v0.x + e1 * v1.x + e2 * v2.x + e3 * v3.x;
            acc_y += e0 * v0.y + e1 * v1.y + e2 * v2.y + e3 * v3.y;
        }
        for (; i < deg; i++) {
            float e0 = s_e[w][i];
            float2 v0 = __bfloat1622float2(hw2[(size_t)s_src[w][i] * 32 + lane]);
            acc_x += e0 * v0.x; acc_y += e0 * v0.y;
        }
    } else {
        float mx = -1e30f;
        for (int i = lane; i < deg; i += 32) {
            float e = asv[g_csrc[start + i]] + adh;
            e = e >= 0.f ? e : 0.2f * e;
            mx = fmaxf(mx, e);
        }
#pragma unroll
        for (int o = 16; o; o >>= 1) mx = fmaxf(mx, __shfl_xor_sync(0xffffffffu, mx, o));
        den = 0.f;
        for (int i = lane; i < deg; i += 32) {
            float e = asv[g_csrc[start + i]] + adh;
            e = e >= 0.f ? e : 0.2f * e;
            den += __expf(e - mx);
        }
#pragma unroll
        for (int o = 16; o; o >>= 1) den += __shfl_xor_sync(0xffffffffu, den, o);
        for (int i = 0; i < deg; i++) {
            int s = g_csrc[start + i];
            float e = asv[s] + adh;
            e = e >= 0.f ? e : 0.2f * e;
            float ex = __expf(e - mx);
            float2 v0 = __bfloat1622float2(hw2[(size_t)s * 32 + lane]);
            acc_x += ex * v0.x; acc_y += ex * v0.y;
        }
    }
    float sc = 1.f / (den + 1e-16f);
    float2 b = reinterpret_cast<const float2*>(bias)[lane];
    float2 r;
    r.x = acc_x * sc + b.x;
    r.y = acc_y * sc + b.y;
    reinterpret_cast<float2*>(out)[(size_t)node * 32 + lane] = r;
}

// ---------------- global mean pool (two-stage, batch is sorted) ----------------
__global__ void pool_kernel(const int* __restrict__ batch) {
    __shared__ float sacc[NGRAPH * 64];
    __shared__ float scnt[NGRAPH];
    int t = threadIdx.x;  // 64 threads
    for (int i = t; i < NGRAPH * 64; i += 64) sacc[i] = 0.f;
    if (t < NGRAPH) scnt[t] = 0.f;
    __syncthreads();
    int n0 = blockIdx.x * 256;
    int n1 = min(n0 + 256, NNODES);
    int bmin = NGRAPH, bmax = -1;
    for (int n = n0; n < n1; n++) {
        int b = batch[n];
        sacc[b * 64 + t] += g_h3[(size_t)n * 64 + t];
        if (t == 0) scnt[b] += 1.f;
        bmin = min(bmin, b); bmax = max(bmax, b);
    }
    __syncthreads();
    for (int b = bmin; b <= bmax; b++) {
        atomicAdd(&g_pool[b * 64 + t], sacc[b * 64 + t]);
        if (t == 0) atomicAdd(&g_pool[NGRAPH * 64 + b], scnt[b]);
    }
}

// ---------------- decoder ----------------
__global__ void decoder_kernel(
    const float* __restrict__ gf, const float* __restrict__ Wg, const float* __restrict__ bg,
    const float* __restrict__ Wd1, const float* __restrict__ bd1,
    const float* __restrict__ gamma, const float* __restrict__ beta,
    const float* __restrict__ Wd2, const float* __restrict__ bd2,
    float* __restrict__ out)
{
    __shared__ float z[NGRAPH][128];
    __shared__ float z2[NGRAPH][64];
    __shared__ float logits[NGRAPH][256];
    int t = threadIdx.x;  // 256
    for (int idx = t; idx < NGRAPH * 64; idx += 256) {
        int g = idx / 64, c = idx % 64;
        float cnt = g_pool[NGRAPH * 64 + g];
        z[g][c] = g_pool[idx] / fmaxf(cnt, 1.0f);
        float s = bg[c];
        for (int k = 0; k < 4; k++) s += gf[g * 4 + k] * Wg[k * 64 + c];
        z[g][64 + c] = fmaxf(s, 0.f);
    }
    __syncthreads();
    for (int idx = t; idx < NGRAPH * 64; idx += 256) {
        int g = idx / 64, c = idx % 64;
        float s = bd1[c];
        for (int k = 0; k < 128; k++) s += z[g][k] * Wd1[k * 64 + c];
        s = s * gamma[c] + beta[c];
        z2[g][c] = fmaxf(s, 0.f);
    }
    __syncthreads();
    for (int idx = t; idx < NGRAPH * 256; idx += 256) {
        int g = idx / 256, o = idx % 256;
        float s = bd2[o];
        for (int k = 0; k < 64; k++) s += z2[g][k] * Wd2[k * 256 + o];
        logits[g][o] = s;
    }
    __syncthreads();
    int warp = t >> 5, lane = t & 31;
    for (int g = warp; g < NGRAPH; g += 8) {
        float m = -1e30f;
        for (int o = lane; o < 256; o += 32) m = fmaxf(m, logits[g][o]);
#pragma unroll
        for (int off = 16; off; off >>= 1) m = fmaxf(m, __shfl_xor_sync(0xffffffffu, m, off));
        float s = 0.f;
        for (int o = lane; o < 256; o += 32) s += __expf(logits[g][o] - m);
#pragma unroll
        for (int off = 16; off; off >>= 1) s += __shfl_xor_sync(0xffffffffu, s, off);
        float inv = 1.f / s;
        for (int o = lane; o < 256; o += 32) out[g * 256 + o] = __expf(logits[g][o] - m) * inv;
    }
}

// ---------------- launch ----------------
extern "C" void kernel_launch(void* const* d_in, const int* in_sizes, int n_in,
                              void* d_out, int out_size)
{
    const float* x    = (const float*)d_in[0];
    const int*   ei   = (const int*)d_in[1];
    const int*   batch = (const int*)d_in[2];
    const float* gf   = (const float*)d_in[3];
    const float* W_enc = (const float*)d_in[4];
    const float* b_enc = (const float*)d_in[5];
    const float* W1  = (const float*)d_in[6];
    const float* as1 = (const float*)d_in[7];
    const float* ad1 = (const float*)d_in[8];
    const float* b1  = (const float*)d_in[9];
    const float* W2  = (const float*)d_in[10];
    const float* as2 = (const float*)d_in[11];
    const float* ad2 = (const float*)d_in[12];
    const float* b2  = (const float*)d_in[13];
    const float* W3  = (const float*)d_in[14];
    const float* as3 = (const float*)d_in[15];
    const float* ad3 = (const float*)d_in[16];
    const float* b3  = (const float*)d_in[17];
    const float* Wg  = (const float*)d_in[18];
    const float* bg  = (const float*)d_in[19];
    const float* Wd1 = (const float*)d_in[20];
    const float* bd1 = (const float*)d_in[21];
    const float* gamma = (const float*)d_in[22];
    const float* beta  = (const float*)d_in[23];
    const float* Wd2 = (const float*)d_in[24];
    const float* bd2 = (const float*)d_in[25];
    float* out = (float*)d_out;

    void *p;
    cudaGetSymbolAddress(&p, g_h0);   __nv_bfloat16* h0   = (__nv_bfloat16*)p;
    cudaGetSymbolAddress(&p, g_bufA); __nv_bfloat16* bufA = (__nv_bfloat16*)p;
    cudaGetSymbolAddress(&p, g_bufB); __nv_bfloat16* bufB = (__nv_bfloat16*)p;
    cudaGetSymbolAddress(&p, g_h3);   float* h3  = (float*)p;
    cudaGetSymbolAddress(&p, g_asA);  float* asA = (float*)p;
    cudaGetSymbolAddress(&p, g_adA);  float* adA = (float*)p;
    cudaGetSymbolAddress(&p, g_Wp);   unsigned* Wp = (unsigned*)p;
    float* as_s0 = asA;                  float* ad_s0 = adA;
    float* as_s1 = asA + NNODES * 4;     float* ad_s1 = adA + NNODES * 4;
    float* as_s2 = asA + 2 * NNODES * 4; float* ad_s2 = adA + 2 * NNODES * 4;

    static bool attr_done = false;
    if (!attr_done) {
        cudaFuncSetAttribute(scan_kernel, cudaFuncAttributeMaxDynamicSharedMemorySize,
                             NNODES * (int)sizeof(int));
        attr_done = true;
    }

    // fork CSR chain at graph start (side stream), main stream does pool zero + packW
    cudaEventRecord(g_sb.ev_fork, 0);
    cudaStreamWaitEvent(g_sb.s2, g_sb.ev_fork, 0);
    zero_csr_kernel<<<(NNODES + 255) / 256, 256, 0, g_sb.s2>>>();
    deg_kernel<<<(ETOT + 255) / 256, 256, 0, g_sb.s2>>>(ei);
    scan_kernel<<<1, 1024, NNODES * sizeof(int), g_sb.s2>>>();
    fill_kernel<<<(ETOT + 255) / 256, 256, 0, g_sb.s2>>>(ei);
    cudaEventRecord(g_sb.ev_join, g_sb.s2);

    zero_pool_kernel<<<(NGRAPH * 64 + NGRAPH + 255) / 256, 256>>>();
    packW_all_kernel<<<(WP_TOT + 255) / 256, 256>>>(W_enc, W1, W2, W3);

    dim3 blk(256);
    int mg = (NNODES + BM - 1) / BM;
    // encoder: h0(bf16) = x @ W_enc + b_enc   (fp32 A path)
    gemm_kernel<true, true, false, false><<<dim3(1, mg), blk>>>(
        x, Wp + OFF_ENC, b_enc, h0, NNODES, 32, 64, nullptr, nullptr, nullptr, nullptr, 0);

    // conv1 GEMM (bf16 A) + fused attention
    gemm_kernel<false, true, true, true><<<dim3(4, mg), blk>>>(
        h0, Wp + OFF_W1, nullptr, bufB, NNODES, 64, 256, as1, ad1, as_s0, ad_s0, 4);

    // join CSR before aggregation
    cudaStreamWaitEvent(0, g_sb.ev_join, 0);
    agg4_kernel<<<NNODES / 4, 256>>>(bufB, as_s0, ad_s0, b1, bufA);

    // conv2
    gemm_kernel<false, true, true, true><<<dim3(4, mg), blk>>>(
        bufA, Wp + OFF_W2, nullptr, bufB, NNODES, 256, 256, as2, ad2, as_s1, ad_s1, 4);
    agg4_kernel<<<NNODES / 4, 256>>>(bufB, as_s1, ad_s1, b2, bufA);

    // conv3
    gemm_kernel<false, true, true, true><<<dim3(1, mg), blk>>>(
        bufA, Wp + OFF_W3, nullptr, bufB, NNODES, 256, 64, as3, ad3, as_s2, ad_s2, 1);
    agg1_kernel<<<(NNODES + 1) / 2, 64>>>(bufB, as_s2, ad_s2, b3, h3);

    // pooling + decoder (two-stage; low-contention atomics)
    pool_kernel<<<(NNODES + 255) / 256, 64>>>(batch);
    decoder_kernel<<<1, 256>>>(gf, Wg, bg, Wd1, bd1, gamma, beta, Wd2, bd2, out);
}

// round 14
// speedup vs baseline: 1.0424x; 1.0424x over previous
#include <cuda_runtime.h>
#include <cuda_bf16.h>

#define NNODES 50000
#define NEDGES 800000
#define ETOT   (NNODES + NEDGES)
#define NGRAPH 16
#define CAP    128

// packed-weight offsets (unsigned = bf16x2 along K)
#define OFF_ENC 0        // 16*64   = 1024
#define OFF_W1  1024     // 32*256  = 8192
#define OFF_W2  9216     // 128*256 = 32768
#define OFF_W3  41984    // 128*64  = 8192
#define WP_TOT  50176

// ---------------- scratch (device globals; allocation-free rule) ----------------
__device__ __align__(128) __nv_bfloat16 g_h0[NNODES * 64];      // encoder output (bf16)
__device__ __align__(128) __nv_bfloat16 g_bufA[NNODES * 256];   // conv outputs (bf16)
__device__ __align__(128) __nv_bfloat16 g_bufB[NNODES * 256];   // h @ W (bf16, per-conv)
__device__ __align__(128) float g_h3[NNODES * 64];              // conv3 output (fp32)
__device__ __align__(128) unsigned g_Wp[WP_TOT];                // packed bf16 weights
__device__ float g_asA[3 * NNODES * 4];
__device__ float g_adA[3 * NNODES * 4];
__device__ int   g_deg[NNODES];
__device__ int   g_fill[NNODES];
__device__ int   g_rowptr[NNODES + 1];
__device__ int   g_csrc[ETOT];
__device__ float g_pool[NGRAPH * 64 + NGRAPH];  // sums then counts

// ---------------- side stream for CSR/GEMM overlap ----------------
struct StreamBundle {
    cudaStream_t s2;
    cudaEvent_t ev_fork, ev_join;
    StreamBundle() {
        cudaStreamCreateWithFlags(&s2, cudaStreamNonBlocking);
        cudaEventCreateWithFlags(&ev_fork, cudaEventDisableTiming);
        cudaEventCreateWithFlags(&ev_join, cudaEventDisableTiming);
    }
};
static StreamBundle g_sb;

__device__ __forceinline__ unsigned pack_bf2(float x, float y) {
    __nv_bfloat162 t = __floats2bfloat162_rn(x, y);
    return *reinterpret_cast<unsigned*>(&t);
}

// ---------------- setup (split: CSR zeros on side stream, pool zeros on main) ----
__global__ void zero_csr_kernel() {
    int i = blockIdx.x * blockDim.x + threadIdx.x;
    if (i < NNODES) { g_deg[i] = 0; g_fill[i] = 0; }
}
__global__ void zero_pool_kernel() {
    int i = blockIdx.x * blockDim.x + threadIdx.x;
    if (i < NGRAPH * 64 + NGRAPH) g_pool[i] = 0.f;
}

// ---------------- pack all weights to bf16 K-pairs, [n][kp] layout ----------------
__global__ void packW_all_kernel(const float* __restrict__ Wenc,
                                 const float* __restrict__ W1,
                                 const float* __restrict__ W2,
                                 const float* __restrict__ W3) {
    int idx = blockIdx.x * blockDim.x + threadIdx.x;
    if (idx >= WP_TOT) return;
    const float* W; int Kd2, Nd; unsigned* dst; int local;
    if (idx < OFF_W1)       { W = Wenc; Kd2 = 16;  Nd = 64;  dst = g_Wp + OFF_ENC; local = idx - OFF_ENC; }
    else if (idx < OFF_W2)  { W = W1;   Kd2 = 32;  Nd = 256; dst = g_Wp + OFF_W1;  local = idx - OFF_W1; }
    else if (idx < OFF_W3)  { W = W2;   Kd2 = 128; Nd = 256; dst = g_Wp + OFF_W2;  local = idx - OFF_W2; }
    else                    { W = W3;   Kd2 = 128; Nd = 64;  dst = g_Wp + OFF_W3;  local = idx - OFF_W3; }
    int n = local / Kd2, kp = local % Kd2;
    dst[local] = pack_bf2(W[(size_t)(2 * kp) * Nd + n], W[(size_t)(2 * kp + 1) * Nd + n]);
}

// ---------------- CSR build ----------------
__global__ void deg_kernel(const int* __restrict__ ei) {
    int e = blockIdx.x * blockDim.x + threadIdx.x;
    if (e >= ETOT) return;
    int dst = (e < NEDGES) ? ei[NEDGES + e] : (e - NEDGES);
    atomicAdd(&g_deg[dst], 1);
}

// smem-staged single-block scan: coalesced global IO, chunk-sequential work in smem
__global__ void scan_kernel() {
    extern __shared__ int sdeg[];   // NNODES ints (200 KB)
    __shared__ int warp_sums[32];
    int t = threadIdx.x;
    for (int i = t; i < NNODES; i += 1024) sdeg[i] = g_deg[i];
    __syncthreads();

    const int PER = (NNODES + 1023) / 1024;  // 49
    int start = t * PER;
    int end = min(start + PER, NNODES);
    int local = 0;
    for (int i = start; i < end; i++) local += sdeg[i];

    int lane = t & 31, w = t >> 5;
    int v = local;
#pragma unroll
    for (int off = 1; off < 32; off <<= 1) {
        int n = __shfl_up_sync(0xffffffffu, v, off);
        if (lane >= off) v += n;
    }
    if (lane == 31) warp_sums[w] = v;
    __syncthreads();
    if (w == 0) {
        int s = warp_sums[lane];
#pragma unroll
        for (int off = 1; off < 32; off <<= 1) {
            int n = __shfl_up_sync(0xffffffffu, s, off);
            if (lane >= off) s += n;
        }
        warp_sums[lane] = s;
    }
    __syncthreads();
    int excl = v - local + (w > 0 ? warp_sums[w - 1] : 0);

    int run = excl;
    for (int i = start; i < end; i++) { int d = sdeg[i]; sdeg[i] = run; run += d; }
    if (end == NNODES && start < NNODES) g_rowptr[NNODES] = run;
    __syncthreads();
    for (int i = t; i < NNODES; i += 1024) g_rowptr[i] = sdeg[i];
}

__global__ void fill_kernel(const int* __restrict__ ei) {
    int e = blockIdx.x * blockDim.x + threadIdx.x;
    if (e >= ETOT) return;
    int src, dst;
    if (e < NEDGES) { src = ei[e]; dst = ei[NEDGES + e]; }
    else            { src = dst = e - NEDGES; }
    int pos = g_rowptr[dst] + atomicAdd(&g_fill[dst], 1);
    g_csrc[pos] = src;
}

// ---------------- bf16 tensor-core GEMM (+ fused attention epilogue) ----------------
#define BM 128
#define BN 64
#define BK 32
#define AST 20
#define BST 20

__device__ __forceinline__ void mma_bf16(float* d, const unsigned* a, const unsigned* b) {
    asm volatile(
        "mma.sync.aligned.m16n8k16.row.col.f32.bf16.bf16.f32 "
        "{%0,%1,%2,%3}, {%4,%5,%6,%7}, {%8,%9}, {%0,%1,%2,%3};"
        : "+f"(d[0]), "+f"(d[1]), "+f"(d[2]), "+f"(d[3])
        : "r"(a[0]), "r"(a[1]), "r"(a[2]), "r"(a[3]), "r"(b[0]), "r"(b[1]));
}

// A_BF16: A rows packed bf16; else fp32. B: pre-packed bf16 K-pairs [n][kp].
// OUT_BF16: C is bf16 packed rows. FUSE_ATTN: a_s/a_d direct store (head = bn>>6).
template <bool ADD_BIAS, bool OUT_BF16, bool FUSE_ATTN, bool A_BF16>
__global__ __launch_bounds__(256) void gemm_kernel(
    const void* __restrict__ Av, const unsigned* __restrict__ Bp,
    const float* __restrict__ bias, void* __restrict__ Cv,
    int M, int Kd, int Nd,
    const float* __restrict__ atts, const float* __restrict__ attd,
    float* __restrict__ as_out, float* __restrict__ ad_out, int hstride)
{
    __shared__ unsigned As[BM * AST];
    __shared__ unsigned Bs[BN * BST];

    int t = threadIdx.x;
    int bm = blockIdx.y * BM, bn = blockIdx.x * BN;
    int wid = t >> 5, lane = t & 31;
    int wm = (wid >> 1) * 32, wn = (wid & 1) * 32;
    int r0 = lane >> 2, p = lane & 3;
    int Kd2 = Kd >> 1;

    float acc[2][4][4] = {};
    float4 arf[4];
    uint4  arb[2];
    unsigned br[4];

    auto loadB = [&](int k02) {
#pragma unroll
        for (int i = 0; i < 4; i++) {
            int task = t + i * 256;
            int kp = task & 15, n = task >> 4;
            br[i] = Bp[(size_t)(bn + n) * Kd2 + k02 + kp];
        }
    };
    auto storeB = [&]() {
#pragma unroll
        for (int i = 0; i < 4; i++) {
            int task = t + i * 256;
            int kp = task & 15, n = task >> 4;
            Bs[n * BST + kp] = br[i];
        }
    };

    if (A_BF16) {
        const __nv_bfloat16* A = (const __nv_bfloat16*)Av;
#pragma unroll
        for (int i = 0; i < 2; i++) {
            int idx = t + i * 256;
            int row = idx >> 2, c4 = idx & 3;
            int grow = bm + row;
            arb[i] = (grow < M) ? *reinterpret_cast<const uint4*>(A + (size_t)grow * Kd + c4 * 8)
                                : make_uint4(0u, 0u, 0u, 0u);
        }
    } else {
        const float* A = (const float*)Av;
#pragma unroll
        for (int i = 0; i < 4; i++) {
            int f4 = t + i * 256;
            int row = f4 >> 3, c4 = f4 & 7;
            int grow = bm + row;
            arf[i] = (grow < M) ? *reinterpret_cast<const float4*>(A + (size_t)grow * Kd + c4 * 4)
                                : make_float4(0.f, 0.f, 0.f, 0.f);
        }
    }
    loadB(0);
    if (A_BF16) {
#pragma unroll
        for (int i = 0; i < 2; i++) {
            int idx = t + i * 256;
            int row = idx >> 2, c4 = idx & 3;
            unsigned* dst = &As[row * AST + c4 * 4];
            dst[0] = arb[i].x; dst[1] = arb[i].y; dst[2] = arb[i].z; dst[3] = arb[i].w;
        }
    } else {
#pragma unroll
        for (int i = 0; i < 4; i++) {
            int f4 = t + i * 256;
            int row = f4 >> 3, c4 = f4 & 7;
            As[row * AST + c4 * 2]     = pack_bf2(arf[i].x, arf[i].y);
            As[row * AST + c4 * 2 + 1] = pack_bf2(arf[i].z, arf[i].w);
        }
    }
    storeB();
    __syncthreads();

    int niter = Kd / BK;
    for (int it = 0; it < niter; it++) {
        if (it + 1 < niter) {
            int k0 = (it + 1) * BK;
            if (A_BF16) {
                const __nv_bfloat16* A = (const __nv_bfloat16*)Av;
#pragma unroll
                for (int i = 0; i < 2; i++) {
                    int idx = t + i * 256;
                    int row = idx >> 2, c4 = idx & 3;
                    int grow = bm + row;
                    arb[i] = (grow < M)
                           ? *reinterpret_cast<const uint4*>(A + (size_t)grow * Kd + k0 + c4 * 8)
                           : make_uint4(0u, 0u, 0u, 0u);
                }
            } else {
                const float* A = (const float*)Av;
#pragma unroll
                for (int i = 0; i < 4; i++) {
                    int f4 = t + i * 256;
                    int row = f4 >> 3, c4 = f4 & 7;
                    int grow = bm + row;
                    arf[i] = (grow < M)
                           ? *reinterpret_cast<const float4*>(A + (size_t)grow * Kd + k0 + c4 * 4)
                           : make_float4(0.f, 0.f, 0.f, 0.f);
                }
            }
            loadB((it + 1) * (BK / 2));
        }
#pragma unroll
        for (int ks = 0; ks < 2; ks++) {
            int kb = ks * 8;
            unsigned ah[2][4];
#pragma unroll
            for (int mt = 0; mt < 2; mt++) {
                int base = (wm + mt * 16 + r0) * AST + kb + p;
                ah[mt][0] = As[base];
                ah[mt][1] = As[base + 8 * AST];
                ah[mt][2] = As[base + 4];
                ah[mt][3] = As[base + 8 * AST + 4];
            }
            unsigned bh[4][2];
#pragma unroll
            for (int nt = 0; nt < 4; nt++) {
                int base = (wn + nt * 8 + r0) * BST + kb + p;
                bh[nt][0] = Bs[base];
                bh[nt][1] = Bs[base + 4];
            }
#pragma unroll
            for (int mt = 0; mt < 2; mt++)
#pragma unroll
                for (int nt = 0; nt < 4; nt++)
                    mma_bf16(acc[mt][nt], ah[mt], bh[nt]);
        }
        __syncthreads();
        if (it + 1 < niter) {
            if (A_BF16) {
#pragma unroll
                for (int i = 0; i < 2; i++) {
                    int idx = t + i * 256;
                    int row = idx >> 2, c4 = idx & 3;
                    unsigned* dst = &As[row * AST + c4 * 4];
                    dst[0] = arb[i].x; dst[1] = arb[i].y; dst[2] = arb[i].z; dst[3] = arb[i].w;
                }
            } else {
#pragma unroll
                for (int i = 0; i < 4; i++) {
                    int f4 = t + i * 256;
                    int row = f4 >> 3, c4 = f4 & 7;
                    As[row * AST + c4 * 2]     = pack_bf2(arf[i].x, arf[i].y);
                    As[row * AST + c4 * 2 + 1] = pack_bf2(arf[i].z, arf[i].w);
                }
            }
            storeB();
            __syncthreads();
        }
    }

    // epilogue (+ optional fused attention partials)
    float sA[2] = {0.f, 0.f}, dA[2] = {0.f, 0.f};
    float sB[2] = {0.f, 0.f}, dB[2] = {0.f, 0.f};
    const float* attsh = FUSE_ATTN ? atts + (bn >> 6) * 64 : nullptr;
    const float* attdh = FUSE_ATTN ? attd + (bn >> 6) * 64 : nullptr;
#pragma unroll
    for (int mt = 0; mt < 2; mt++) {
#pragma unroll
        for (int nt = 0; nt < 4; nt++) {
            int grow0 = bm + wm + mt * 16 + r0;
            int gcol = bn + wn + nt * 8 + 2 * p;
            float b0v = 0.f, b1v = 0.f;
            if (ADD_BIAS) { b0v = bias[gcol]; b1v = bias[gcol + 1]; }
            float* c = acc[mt][nt];
            if (FUSE_ATTN) {
                int cih = wn + nt * 8 + 2 * p;
                float a0 = attsh[cih], a1 = attsh[cih + 1];
                float t0 = attdh[cih], t1 = attdh[cih + 1];
                sA[mt] += c[0] * a0 + c[1] * a1;
                dA[mt] += c[0] * t0 + c[1] * t1;
                sB[mt] += c[2] * a0 + c[3] * a1;
                dB[mt] += c[2] * t0 + c[3] * t1;
            }
            if (OUT_BF16) {
                __nv_bfloat162* Cb = (__nv_bfloat162*)Cv;
                if (grow0 < M)
                    Cb[((size_t)grow0 * Nd + gcol) >> 1] = __floats2bfloat162_rn(c[0] + b0v, c[1] + b1v);
                if (grow0 + 8 < M)
                    Cb[((size_t)(grow0 + 8) * Nd + gcol) >> 1] = __floats2bfloat162_rn(c[2] + b0v, c[3] + b1v);
            } else {
                float* C = (float*)Cv;
                if (grow0 < M) {
                    C[(size_t)grow0 * Nd + gcol]     = c[0] + b0v;
                    C[(size_t)grow0 * Nd + gcol + 1] = c[1] + b1v;
                }
                if (grow0 + 8 < M) {
                    C[(size_t)(grow0 + 8) * Nd + gcol]     = c[2] + b0v;
                    C[(size_t)(grow0 + 8) * Nd + gcol + 1] = c[3] + b1v;
                }
            }
        }
    }
    if (FUSE_ATTN) {
        int head = bn >> 6;
#pragma unroll
        for (int mt = 0; mt < 2; mt++) {
            sA[mt] += __shfl_xor_sync(0xffffffffu, sA[mt], 1); sA[mt] += __shfl_xor_sync(0xffffffffu, sA[mt], 2);
            dA[mt] += __shfl_xor_sync(0xffffffffu, dA[mt], 1); dA[mt] += __shfl_xor_sync(0xffffffffu, dA[mt], 2);
            sB[mt] += __shfl_xor_sync(0xffffffffu, sB[mt], 1); sB[mt] += __shfl_xor_sync(0xffffffffu, sB[mt], 2);
            dB[mt] += __shfl_xor_sync(0xffffffffu, dB[mt], 1); dB[mt] += __shfl_xor_sync(0xffffffffu, dB[mt], 2);
        }
        float* s_rs = reinterpret_cast<float*>(As);   // [BM]
        float* s_rd = s_rs + BM;                      // [BM]
        __syncthreads();
        if ((wid & 1) == 0 && p == 0) {
#pragma unroll
            for (int mt = 0; mt < 2; mt++) {
                int r = wm + mt * 16 + r0;
                s_rs[r] = sA[mt];     s_rd[r] = dA[mt];
                s_rs[r + 8] = sB[mt]; s_rd[r + 8] = dB[mt];
            }
        }
        __syncthreads();
        if ((wid & 1) == 1 && p == 0) {
#pragma unroll
            for (int mt = 0; mt < 2; mt++) {
                int r = wm + mt * 16 + r0;
                int gr = bm + r;
                if (gr < M) {
                    as_out[(size_t)gr * hstride + head] = s_rs[r] + sA[mt];
                    ad_out[(size_t)gr * hstride + head] = s_rd[r] + dA[mt];
                }
                if (gr + 8 < M) {
                    as_out[(size_t)(gr + 8) * hstride + head] = s_rs[r + 8] + sB[mt];
                    ad_out[(size_t)(gr + 8) * hstride + head] = s_rd[r + 8] + dB[mt];
                }
            }
        }
    }
}

// ---------------- 4-head aggregation: block(64) per node, bf16 gather, bf16 out ----------------
__global__ __launch_bounds__(64) void agg4_kernel(
    const __nv_bfloat16* __restrict__ hw,
    const float* __restrict__ asv, const float* __restrict__ adv,
    const float* __restrict__ bias, __nv_bfloat16* __restrict__ out)
{
    int node = blockIdx.x;
    int tid = threadIdx.x;
    int start = g_rowptr[node];
    int deg = g_rowptr[node + 1] - start;

    __shared__ int   s_src[CAP];
    __shared__ float s_e[4][CAP];
    __shared__ float s_scale[4], s_m[4], s_adv[4];

    int w = tid >> 5, lane = tid & 31;
    int h3 = tid >> 4;
    float4 acc = make_float4(0.f, 0.f, 0.f, 0.f);
    const uint2* hw8 = reinterpret_cast<const uint2*>(hw);

    if (deg <= CAP) {
        for (int i = tid; i < deg; i += 64) s_src[i] = g_csrc[start + i];
        __syncthreads();
        for (int h = w; h < 4; h += 2) {
            float adh = adv[node * 4 + h];
            float mx = -1e30f;
            for (int i = lane; i < deg; i += 32) {
                float e = asv[s_src[i] * 4 + h] + adh;
                e = e >= 0.f ? e : 0.2f * e;
                s_e[h][i] = e;
                mx = fmaxf(mx, e);
            }
#pragma unroll
            for (int o = 16; o; o >>= 1) mx = fmaxf(mx, __shfl_xor_sync(0xffffffffu, mx, o));
            float den = 0.f;
            for (int i = lane; i < deg; i += 32) {
                float ex = __expf(s_e[h][i] - mx);
                s_e[h][i] = ex;
                den += ex;
            }
#pragma unroll
            for (int o = 16; o; o >>= 1) den += __shfl_xor_sync(0xffffffffu, den, o);
            if (lane == 0) s_scale[h] = 1.f / (den + 1e-16f);
        }
        __syncthreads();
        const float* eh = s_e[h3];
        int i = 0;
        for (; i + 4 <= deg; i += 4) {
            int s0 = s_src[i], s1 = s_src[i + 1], s2 = s_src[i + 2], s3 = s_src[i + 3];
            float e0 = eh[i], e1 = eh[i + 1], e2 = eh[i + 2], e3 = eh[i + 3];
            uint2 u0 = hw8[(size_t)s0 * 64 + tid];
            uint2 u1 = hw8[(size_t)s1 * 64 + tid];
            uint2 u2 = hw8[(size_t)s2 * 64 + tid];
            uint2 u3 = hw8[(size_t)s3 * 64 + tid];
            float2 a0 = __bfloat1622float2(*reinterpret_cast<__nv_bfloat162*>(&u0.x));
            float2 b0 = __bfloat1622float2(*reinterpret_cast<__nv_bfloat162*>(&u0.y));
            float2 a1 = __bfloat1622float2(*reinterpret_cast<__nv_bfloat162*>(&u1.x));
            float2 b1 = __bfloat1622float2(*reinterpret_cast<__nv_bfloat162*>(&u1.y));
            float2 a2 = __bfloat1622float2(*reinterpret_cast<__nv_bfloat162*>(&u2.x));
            float2 b2 = __bfloat1622float2(*reinterpret_cast<__nv_bfloat162*>(&u2.y));
            float2 a3 = __bfloat1622float2(*reinterpret_cast<__nv_bfloat162*>(&u3.x));
            float2 b3 = __bfloat1622float2(*reinterpret_cast<__nv_bfloat162*>(&u3.y));
            acc.x += e0 * a0.x + e1 * a1.x + e2 * a2.x + e3 * a3.x;
            acc.y += e0 * a0.y + e1 * a1.y + e2 * a2.y + e3 * a3.y;
            acc.z += e0 * b0.x + e1 * b1.x + e2 * b2.x + e3 * b3.x;
            acc.w += e0 * b0.y + e1 * b1.y + e2 * b2.y + e3 * b3.y;
        }
        for (; i < deg; i++) {
            float e0 = eh[i];
            uint2 u0 = hw8[(size_t)s_src[i] * 64 + tid];
            float2 a0 = __bfloat1622float2(*reinterpret_cast<__nv_bfloat162*>(&u0.x));
            float2 b0 = __bfloat1622float2(*reinterpret_cast<__nv_bfloat162*>(&u0.y));
            acc.x += e0 * a0.x; acc.y += e0 * a0.y;
            acc.z += e0 * b0.x; acc.w += e0 * b0.y;
        }
    } else {
        for (int h = w; h < 4; h += 2) {
            float adh = adv[node * 4 + h];
            float mx = -1e30f;
            for (int i = lane; i < deg; i += 32) {
                float e = asv[g_csrc[start + i] * 4 + h] + adh;
                e = e >= 0.f ? e : 0.2f * e;
                mx = fmaxf(mx, e);
            }
#pragma unroll
            for (int o = 16; o; o >>= 1) mx = fmaxf(mx, __shfl_xor_sync(0xffffffffu, mx, o));
            float den = 0.f;
            for (int i = lane; i < deg; i += 32) {
                float e = asv[g_csrc[start + i] * 4 + h] + adh;
                e = e >= 0.f ? e : 0.2f * e;
                den += __expf(e - mx);
            }
#pragma unroll
            for (int o = 16; o; o >>= 1) den += __shfl_xor_sync(0xffffffffu, den, o);
            if (lane == 0) {
                s_m[h] = mx;
                s_scale[h] = 1.f / (den + 1e-16f);
                s_adv[h] = adh;
            }
        }
        __syncthreads();
        float mxh = s_m[h3], adh = s_adv[h3];
        for (int i = 0; i < deg; i++) {
            int s = g_csrc[start + i];
            float e = asv[s * 4 + h3] + adh;
            e = e >= 0.f ? e : 0.2f * e;
            float ex = __expf(e - mxh);
            uint2 u0 = hw8[(size_t)s * 64 + tid];
            float2 a0 = __bfloat1622float2(*reinterpret_cast<__nv_bfloat162*>(&u0.x));
            float2 b0 = __bfloat1622float2(*reinterpret_cast<__nv_bfloat162*>(&u0.y));
            acc.x += ex * a0.x; acc.y += ex * a0.y;
            acc.z += ex * b0.x; acc.w += ex * b0.y;
        }
    }

    float sc = s_scale[h3];
    float4 b = reinterpret_cast<const float4*>(bias)[tid];
    acc.x = acc.x * sc + b.x;
    acc.y = acc.y * sc + b.y;
    acc.z = acc.z * sc + b.z;
    acc.w = acc.w * sc + b.w;
    acc.x = acc.x > 0.f ? acc.x : (__expf(acc.x) - 1.f);
    acc.y = acc.y > 0.f ? acc.y : (__expf(acc.y) - 1.f);
    acc.z = acc.z > 0.f ? acc.z : (__expf(acc.z) - 1.f);
    acc.w = acc.w > 0.f ? acc.w : (__expf(acc.w) - 1.f);
    __nv_bfloat162 p0 = __floats2bfloat162_rn(acc.x, acc.y);
    __nv_bfloat162 p1 = __floats2bfloat162_rn(acc.z, acc.w);
    uint2 o;
    o.x = *reinterpret_cast<unsigned*>(&p0);
    o.y = *reinterpret_cast<unsigned*>(&p1);
    reinterpret_cast<uint2*>(out)[(size_t)node * 64 + tid] = o;
}

// ---------------- 1-head aggregation: warp per node, bf162 gather, fp32 out ----------------
__global__ __launch_bounds__(64) void agg1_kernel(
    const __nv_bfloat16* __restrict__ hw,
    const float* __restrict__ asv, const float* __restrict__ adv,
    const float* __restrict__ bias, float* __restrict__ out)
{
    __shared__ int   s_src[2][CAP];
    __shared__ float s_e[2][CAP];
    int w = threadIdx.x >> 5, lane = threadIdx.x & 31;
    int node = blockIdx.x * 2 + w;
    if (node >= NNODES) return;
    int start = g_rowptr[node];
    int deg = g_rowptr[node + 1] - start;
    float adh = adv[node];

    float acc_x = 0.f, acc_y = 0.f;
    float den;
    const __nv_bfloat162* hw2 = reinterpret_cast<const __nv_bfloat162*>(hw);

    if (deg <= CAP) {
        float mx = -1e30f;
        for (int i = lane; i < deg; i += 32) {
            int s = g_csrc[start + i];
            s_src[w][i] = s;
            float e = asv[s] + adh;
            e = e >= 0.f ? e : 0.2f * e;
            s_e[w][i] = e;
            mx = fmaxf(mx, e);
        }
#pragma unroll
        for (int o = 16; o; o >>= 1) mx = fmaxf(mx, __shfl_xor_sync(0xffffffffu, mx, o));
        __syncwarp();
        den = 0.f;
        for (int i = lane; i < deg; i += 32) {
            float ex = __expf(s_e[w][i] - mx);
            s_e[w][i] = ex;
            den += ex;
        }
#pragma unroll
        for (int o = 16; o; o >>= 1) den += __shfl_xor_sync(0xffffffffu, den, o);
        __syncwarp();
        int i = 0;
        for (; i + 4 <= deg; i += 4) {
            int s0 = s_src[w][i], s1 = s_src[w][i + 1], s2 = s_src[w][i + 2], s3 = s_src[w][i + 3];
            float e0 = s_e[w][i], e1 = s_e[w][i + 1], e2 = s_e[w][i + 2], e3 = s_e[w][i + 3];
            float2 v0 = __bfloat1622float2(hw2[(size_t)s0 * 32 + lane]);
            float2 v1 = __bfloat1622float2(hw2[(size_t)s1 * 32 + lane]);
            float2 v2 = __bfloat1622float2(hw2[(size_t)s2 * 32 + lane]);
            float2 v3 = __bfloat1622float2(hw2[(size_t)s3 * 32 + lane]);
            acc_x += e0 * v0.x + e1 * v1.x + e2 * v2.x + e3 * v3.x;
            acc_y += e0 * v0.y + e1 * v1.y + e2 * v2.y + e3 * v3.y;
        }
        for (; i < deg; i++) {
            float e0 = s_e[w][i];
            float2 v0 = __bfloat1622float2(hw2[(size_t)s_src[w][i] * 32 + lane]);
            acc_x += e0 * v0.x; acc_y += e0 * v0.y;
        }
    } else {
        float mx = -1e30f;
        for (int i = lane; i < deg; i += 32) {
            float e = asv[g_csrc[start + i]] + adh;
            e = e >= 0.f ? e : 0.2f * e;
            mx = fmaxf(mx, e);
        }
#pragma unroll
        for (int o = 16; o; o >>= 1) mx = fmaxf(mx, __shfl_xor_sync(0xffffffffu, mx, o));
        den = 0.f;
        for (int i = lane; i < deg; i += 32) {
            float e = asv[g_csrc[start + i]] + adh;
            e = e >= 0.f ? e : 0.2f * e;
            den += __expf(e - mx);
        }
#pragma unroll
        for (int o = 16; o; o >>= 1) den += __shfl_xor_sync(0xffffffffu, den, o);
        for (int i = 0; i < deg; i++) {
            int s = g_csrc[start + i];
            float e = asv[s] + adh;
            e = e >= 0.f ? e : 0.2f * e;
            float ex = __expf(e - mx);
            float2 v0 = __bfloat1622float2(hw2[(size_t)s * 32 + lane]);
            acc_x += ex * v0.x; acc_y += ex * v0.y;
        }
    }
    float sc = 1.f / (den + 1e-16f);
    float2 b = reinterpret_cast<const float2*>(bias)[lane];
    float2 r;
    r.x = acc_x * sc + b.x;
    r.y = acc_y * sc + b.y;
    reinterpret_cast<float2*>(out)[(size_t)node * 32 + lane] = r;
}

// ---------------- global mean pool (two-stage, batch is sorted) ----------------
__global__ void pool_kernel(const int* __restrict__ batch) {
    __shared__ float sacc[NGRAPH * 64];
    __shared__ float scnt[NGRAPH];
    int t = threadIdx.x;  // 64 threads
    for (int i = t; i < NGRAPH * 64; i += 64) sacc[i] = 0.f;
    if (t < NGRAPH) scnt[t] = 0.f;
    __syncthreads();
    int n0 = blockIdx.x * 256;
    int n1 = min(n0 + 256, NNODES);
    int bmin = NGRAPH, bmax = -1;
    for (int n = n0; n < n1; n++) {
        int b = batch[n];
        sacc[b * 64 + t] += g_h3[(size_t)n * 64 + t];
        if (t == 0) scnt[b] += 1.f;
        bmin = min(bmin, b); bmax = max(bmax, b);
    }
    __syncthreads();
    for (int b = bmin; b <= bmax; b++) {
        atomicAdd(&g_pool[b * 64 + t], sacc[b * 64 + t]);
        if (t == 0) atomicAdd(&g_pool[NGRAPH * 64 + b], scnt[b]);
    }
}

// ---------------- decoder ----------------
__global__ void decoder_kernel(
    const float* __restrict__ gf, const float* __restrict__ Wg, const float* __restrict__ bg,
    const float* __restrict__ Wd1, const float* __restrict__ bd1,
    const float* __restrict__ gamma, const float* __restrict__ beta,
    const float* __restrict__ Wd2, const float* __restrict__ bd2,
    float* __restrict__ out)
{
    __shared__ float z[NGRAPH][128];
    __shared__ float z2[NGRAPH][64];
    __shared__ float logits[NGRAPH][256];
    int t = threadIdx.x;  // 256
    for (int idx = t; idx < NGRAPH * 64; idx += 256) {
        int g = idx / 64, c = idx % 64;
        float cnt = g_pool[NGRAPH * 64 + g];
        z[g][c] = g_pool[idx] / fmaxf(cnt, 1.0f);
        float s = bg[c];
        for (int k = 0; k < 4; k++) s += gf[g * 4 + k] * Wg[k * 64 + c];
        z[g][64 + c] = fmaxf(s, 0.f);
    }
    __syncthreads();
    for (int idx = t; idx < NGRAPH * 64; idx += 256) {
        int g = idx / 64, c = idx % 64;
        float s = bd1[c];
        for (int k = 0; k < 128; k++) s += z[g][k] * Wd1[k * 64 + c];
        s = s * gamma[c] + beta[c];
        z2[g][c] = fmaxf(s, 0.f);
    }
    __syncthreads();
    for (int idx = t; idx < NGRAPH * 256; idx += 256) {
        int g = idx / 256, o = idx % 256;
        float s = bd2[o];
        for (int k = 0; k < 64; k++) s += z2[g][k] * Wd2[k * 256 + o];
        logits[g][o] = s;
    }
    __syncthreads();
    int warp = t >> 5, lane = t & 31;
    for (int g = warp; g < NGRAPH; g += 8) {
        float m = -1e30f;
        for (int o = lane; o < 256; o += 32) m = fmaxf(m, logits[g][o]);
#pragma unroll
        for (int off = 16; off; off >>= 1) m = fmaxf(m, __shfl_xor_sync(0xffffffffu, m, off));
        float s = 0.f;
        for (int o = lane; o < 256; o += 32) s += __expf(logits[g][o] - m);
#pragma unroll
        for (int off = 16; off; off >>= 1) s += __shfl_xor_sync(0xffffffffu, s, off);
        float inv = 1.f / s;
        for (int o = lane; o < 256; o += 32) out[g * 256 + o] = __expf(logits[g][o] - m) * inv;
    }
}

// ---------------- launch ----------------
extern "C" void kernel_launch(void* const* d_in, const int* in_sizes, int n_in,
                              void* d_out, int out_size)
{
    const float* x    = (const float*)d_in[0];
    const int*   ei   = (const int*)d_in[1];
    const int*   batch = (const int*)d_in[2];
    const float* gf   = (const float*)d_in[3];
    const float* W_enc = (const float*)d_in[4];
    const float* b_enc = (const float*)d_in[5];
    const float* W1  = (const float*)d_in[6];
    const float* as1 = (const float*)d_in[7];
    const float* ad1 = (const float*)d_in[8];
    const float* b1  = (const float*)d_in[9];
    const float* W2  = (const float*)d_in[10];
    const float* as2 = (const float*)d_in[11];
    const float* ad2 = (const float*)d_in[12];
    const float* b2  = (const float*)d_in[13];
    const float* W3  = (const float*)d_in[14];
    const float* as3 = (const float*)d_in[15];
    const float* ad3 = (const float*)d_in[16];
    const float* b3  = (const float*)d_in[17];
    const float* Wg  = (const float*)d_in[18];
    const float* bg  = (const float*)d_in[19];
    const float* Wd1 = (const float*)d_in[20];
    const float* bd1 = (const float*)d_in[21];
    const float* gamma = (const float*)d_in[22];
    const float* beta  = (const float*)d_in[23];
    const float* Wd2 = (const float*)d_in[24];
    const float* bd2 = (const float*)d_in[25];
    float* out = (float*)d_out;

    void *p;
    cudaGetSymbolAddress(&p, g_h0);   __nv_bfloat16* h0   = (__nv_bfloat16*)p;
    cudaGetSymbolAddress(&p, g_bufA); __nv_bfloat16* bufA = (__nv_bfloat16*)p;
    cudaGetSymbolAddress(&p, g_bufB); __nv_bfloat16* bufB = (__nv_bfloat16*)p;
    cudaGetSymbolAddress(&p, g_h3);   float* h3  = (float*)p;
    cudaGetSymbolAddress(&p, g_asA);  float* asA = (float*)p;
    cudaGetSymbolAddress(&p, g_adA);  float* adA = (float*)p;
    cudaGetSymbolAddress(&p, g_Wp);   unsigned* Wp = (unsigned*)p;
    float* as_s0 = asA;                  float* ad_s0 = adA;
    float* as_s1 = asA + NNODES * 4;     float* ad_s1 = adA + NNODES * 4;
    float* as_s2 = asA + 2 * NNODES * 4; float* ad_s2 = adA + 2 * NNODES * 4;

    static bool attr_done = false;
    if (!attr_done) {
        cudaFuncSetAttribute(scan_kernel, cudaFuncAttributeMaxDynamicSharedMemorySize,
                             NNODES * (int)sizeof(int));
        attr_done = true;
    }

    // fork CSR chain at graph start (side stream), main stream does pool zero + packW
    cudaEventRecord(g_sb.ev_fork, 0);
    cudaStreamWaitEvent(g_sb.s2, g_sb.ev_fork, 0);
    zero_csr_kernel<<<(NNODES + 255) / 256, 256, 0, g_sb.s2>>>();
    deg_kernel<<<(ETOT + 255) / 256, 256, 0, g_sb.s2>>>(ei);
    scan_kernel<<<1, 1024, NNODES * sizeof(int), g_sb.s2>>>();
    fill_kernel<<<(ETOT + 255) / 256, 256, 0, g_sb.s2>>>(ei);
    cudaEventRecord(g_sb.ev_join, g_sb.s2);

    zero_pool_kernel<<<(NGRAPH * 64 + NGRAPH + 255) / 256, 256>>>();
    packW_all_kernel<<<(WP_TOT + 255) / 256, 256>>>(W_enc, W1, W2, W3);

    dim3 blk(256);
    int mg = (NNODES + BM - 1) / BM;
    // encoder: h0(bf16) = x @ W_enc + b_enc   (fp32 A path)
    gemm_kernel<true, true, false, false><<<dim3(1, mg), blk>>>(
        x, Wp + OFF_ENC, b_enc, h0, NNODES, 32, 64, nullptr, nullptr, nullptr, nullptr, 0);

    // conv1 GEMM (bf16 A) + fused attention
    gemm_kernel<false, true, true, true><<<dim3(4, mg), blk>>>(
        h0, Wp + OFF_W1, nullptr, bufB, NNODES, 64, 256, as1, ad1, as_s0, ad_s0, 4);

    // join CSR before aggregation
    cudaStreamWaitEvent(0, g_sb.ev_join, 0);
    agg4_kernel<<<NNODES, 64>>>(bufB, as_s0, ad_s0, b1, bufA);

    // conv2
    gemm_kernel<false, true, true, true><<<dim3(4, mg), blk>>>(
        bufA, Wp + OFF_W2, nullptr, bufB, NNODES, 256, 256, as2, ad2, as_s1, ad_s1, 4);
    agg4_kernel<<<NNODES, 64>>>(bufB, as_s1, ad_s1, b2, bufA);

    // conv3
    gemm_kernel<false, true, true, true><<<dim3(1, mg), blk>>>(
        bufA, Wp + OFF_W3, nullptr, bufB, NNODES, 256, 64, as3, ad3, as_s2, ad_s2, 1);
    agg1_kernel<<<(NNODES + 1) / 2, 64>>>(bufB, as_s2, ad_s2, b3, h3);

    // pooling + decoder (two-stage; low-contention atomics)
    pool_kernel<<<(NNODES + 255) / 256, 64>>>(batch);
    decoder_kernel<<<1, 256>>>(gf, Wg, bg, Wd1, bd1, gamma, beta, Wd2, bd2, out);
}

// round 15
// speedup vs baseline: 1.0794x; 1.0355x over previous
#include <cuda_runtime.h>
#include <cuda_bf16.h>

#define NNODES 50000
#define NEDGES 800000
#define ETOT   (NNODES + NEDGES)
#define NGRAPH 16
#define CAP    128

// packed-weight offsets (unsigned = bf16x2 along K)
#define OFF_ENC 0        // 16*64   = 1024
#define OFF_W1  1024     // 32*256  = 8192
#define OFF_W2  9216     // 128*256 = 32768
#define OFF_W3  41984    // 128*64  = 8192
#define WP_TOT  50176

// ---------------- scratch (device globals; allocation-free rule) ----------------
__device__ __align__(128) __nv_bfloat16 g_h0[NNODES * 64];      // encoder output (bf16)
__device__ __align__(128) __nv_bfloat16 g_bufA[NNODES * 256];   // conv outputs (bf16)
__device__ __align__(128) __nv_bfloat16 g_bufB[NNODES * 256];   // h @ W (bf16, per-conv)
__device__ __align__(128) float g_h3[NNODES * 64];              // conv3 output (fp32)
__device__ __align__(128) unsigned g_Wp[WP_TOT];                // packed bf16 weights
__device__ float g_asA[3 * NNODES * 4];
__device__ float g_adA[3 * NNODES * 4];
__device__ int   g_deg[NNODES];
__device__ int   g_fill[NNODES];
__device__ int   g_rowptr[NNODES + 1];
__device__ int   g_csrc[ETOT];
__device__ float g_pool[NGRAPH * 64 + NGRAPH];  // sums then counts

// ---------------- side stream for CSR/GEMM overlap ----------------
struct StreamBundle {
    cudaStream_t s2;
    cudaEvent_t ev_fork, ev_join;
    StreamBundle() {
        cudaStreamCreateWithFlags(&s2, cudaStreamNonBlocking);
        cudaEventCreateWithFlags(&ev_fork, cudaEventDisableTiming);
        cudaEventCreateWithFlags(&ev_join, cudaEventDisableTiming);
    }
};
static StreamBundle g_sb;

__device__ __forceinline__ unsigned pack_bf2(float x, float y) {
    __nv_bfloat162 t = __floats2bfloat162_rn(x, y);
    return *reinterpret_cast<unsigned*>(&t);
}

// ---------------- setup ----------------
__global__ void zero_setup_kernel() {
    int i = blockIdx.x * blockDim.x + threadIdx.x;
    if (i < NNODES) { g_deg[i] = 0; g_fill[i] = 0; }
    if (i < NGRAPH * 64 + NGRAPH) g_pool[i] = 0.f;
}

// ---------------- pack all weights to bf16 K-pairs, [n][kp] layout ----------------
__global__ void packW_all_kernel(const float* __restrict__ Wenc,
                                 const float* __restrict__ W1,
                                 const float* __restrict__ W2,
                                 const float* __restrict__ W3) {
    int idx = blockIdx.x * blockDim.x + threadIdx.x;
    if (idx >= WP_TOT) return;
    const float* W; int Kd2, Nd; unsigned* dst; int local;
    if (idx < OFF_W1)       { W = Wenc; Kd2 = 16;  Nd = 64;  dst = g_Wp + OFF_ENC; local = idx - OFF_ENC; }
    else if (idx < OFF_W2)  { W = W1;   Kd2 = 32;  Nd = 256; dst = g_Wp + OFF_W1;  local = idx - OFF_W1; }
    else if (idx < OFF_W3)  { W = W2;   Kd2 = 128; Nd = 256; dst = g_Wp + OFF_W2;  local = idx - OFF_W2; }
    else                    { W = W3;   Kd2 = 128; Nd = 64;  dst = g_Wp + OFF_W3;  local = idx - OFF_W3; }
    int n = local / Kd2, kp = local % Kd2;
    dst[local] = pack_bf2(W[(size_t)(2 * kp) * Nd + n], W[(size_t)(2 * kp + 1) * Nd + n]);
}

// ---------------- CSR build ----------------
__global__ void deg_kernel(const int* __restrict__ ei) {
    int e = blockIdx.x * blockDim.x + threadIdx.x;
    if (e >= ETOT) return;
    int dst = (e < NEDGES) ? ei[NEDGES + e] : (e - NEDGES);
    atomicAdd(&g_deg[dst], 1);
}

// smem-staged single-block scan: coalesced global IO, chunk-sequential work in smem
__global__ void scan_kernel() {
    extern __shared__ int sdeg[];   // NNODES ints (200 KB)
    __shared__ int warp_sums[32];
    int t = threadIdx.x;
    for (int i = t; i < NNODES; i += 1024) sdeg[i] = g_deg[i];
    __syncthreads();

    const int PER = (NNODES + 1023) / 1024;  // 49
    int start = t * PER;
    int end = min(start + PER, NNODES);
    int local = 0;
    for (int i = start; i < end; i++) local += sdeg[i];

    int lane = t & 31, w = t >> 5;
    int v = local;
#pragma unroll
    for (int off = 1; off < 32; off <<= 1) {
        int n = __shfl_up_sync(0xffffffffu, v, off);
        if (lane >= off) v += n;
    }
    if (lane == 31) warp_sums[w] = v;
    __syncthreads();
    if (w == 0) {
        int s = warp_sums[lane];
#pragma unroll
        for (int off = 1; off < 32; off <<= 1) {
            int n = __shfl_up_sync(0xffffffffu, s, off);
            if (lane >= off) s += n;
        }
        warp_sums[lane] = s;
    }
    __syncthreads();
    int excl = v - local + (w > 0 ? warp_sums[w - 1] : 0);

    int run = excl;
    for (int i = start; i < end; i++) { int d = sdeg[i]; sdeg[i] = run; run += d; }
    if (end == NNODES && start < NNODES) g_rowptr[NNODES] = run;
    __syncthreads();
    for (int i = t; i < NNODES; i += 1024) g_rowptr[i] = sdeg[i];
}

__global__ void fill_kernel(const int* __restrict__ ei) {
    int e = blockIdx.x * blockDim.x + threadIdx.x;
    if (e >= ETOT) return;
    int src, dst;
    if (e < NEDGES) { src = ei[e]; dst = ei[NEDGES + e]; }
    else            { src = dst = e - NEDGES; }
    int pos = g_rowptr[dst] + atomicAdd(&g_fill[dst], 1);
    g_csrc[pos] = src;
}

// ---------------- bf16 tensor-core GEMM (+ fused attention epilogue) ----------------
#define BM 128
#define BN 64
#define BK 32
#define AST 20
#define BST 20

__device__ __forceinline__ void mma_bf16(float* d, const unsigned* a, const unsigned* b) {
    asm volatile(
        "mma.sync.aligned.m16n8k16.row.col.f32.bf16.bf16.f32 "
        "{%0,%1,%2,%3}, {%4,%5,%6,%7}, {%8,%9}, {%0,%1,%2,%3};"
        : "+f"(d[0]), "+f"(d[1]), "+f"(d[2]), "+f"(d[3])
        : "r"(a[0]), "r"(a[1]), "r"(a[2]), "r"(a[3]), "r"(b[0]), "r"(b[1]));
}

// A_BF16: A rows packed bf16; else fp32. B: pre-packed bf16 K-pairs [n][kp].
// OUT_BF16: C is bf16 packed rows. FUSE_ATTN: a_s/a_d direct store (head = bn>>6).
template <bool ADD_BIAS, bool OUT_BF16, bool FUSE_ATTN, bool A_BF16>
__global__ __launch_bounds__(256) void gemm_kernel(
    const void* __restrict__ Av, const unsigned* __restrict__ Bp,
    const float* __restrict__ bias, void* __restrict__ Cv,
    int M, int Kd, int Nd,
    const float* __restrict__ atts, const float* __restrict__ attd,
    float* __restrict__ as_out, float* __restrict__ ad_out, int hstride)
{
    __shared__ unsigned As[BM * AST];
    __shared__ unsigned Bs[BN * BST];

    int t = threadIdx.x;
    int bm = blockIdx.y * BM, bn = blockIdx.x * BN;
    int wid = t >> 5, lane = t & 31;
    int wm = (wid >> 1) * 32, wn = (wid & 1) * 32;
    int r0 = lane >> 2, p = lane & 3;
    int Kd2 = Kd >> 1;

    float acc[2][4][4] = {};
    float4 arf[4];
    uint4  arb[2];
    unsigned br[4];

    auto loadB = [&](int k02) {
#pragma unroll
        for (int i = 0; i < 4; i++) {
            int task = t + i * 256;
            int kp = task & 15, n = task >> 4;
            br[i] = Bp[(size_t)(bn + n) * Kd2 + k02 + kp];
        }
    };
    auto storeB = [&]() {
#pragma unroll
        for (int i = 0; i < 4; i++) {
            int task = t + i * 256;
            int kp = task & 15, n = task >> 4;
            Bs[n * BST + kp] = br[i];
        }
    };

    if (A_BF16) {
        const __nv_bfloat16* A = (const __nv_bfloat16*)Av;
#pragma unroll
        for (int i = 0; i < 2; i++) {
            int idx = t + i * 256;
            int row = idx >> 2, c4 = idx & 3;
            int grow = bm + row;
            arb[i] = (grow < M) ? *reinterpret_cast<const uint4*>(A + (size_t)grow * Kd + c4 * 8)
                                : make_uint4(0u, 0u, 0u, 0u);
        }
    } else {
        const float* A = (const float*)Av;
#pragma unroll
        for (int i = 0; i < 4; i++) {
            int f4 = t + i * 256;
            int row = f4 >> 3, c4 = f4 & 7;
            int grow = bm + row;
            arf[i] = (grow < M) ? *reinterpret_cast<const float4*>(A + (size_t)grow * Kd + c4 * 4)
                                : make_float4(0.f, 0.f, 0.f, 0.f);
        }
    }
    loadB(0);
    if (A_BF16) {
#pragma unroll
        for (int i = 0; i < 2; i++) {
            int idx = t + i * 256;
            int row = idx >> 2, c4 = idx & 3;
            unsigned* dst = &As[row * AST + c4 * 4];
            dst[0] = arb[i].x; dst[1] = arb[i].y; dst[2] = arb[i].z; dst[3] = arb[i].w;
        }
    } else {
#pragma unroll
        for (int i = 0; i < 4; i++) {
            int f4 = t + i * 256;
            int row = f4 >> 3, c4 = f4 & 7;
            As[row * AST + c4 * 2]     = pack_bf2(arf[i].x, arf[i].y);
            As[row * AST + c4 * 2 + 1] = pack_bf2(arf[i].z, arf[i].w);
        }
    }
    storeB();
    __syncthreads();

    int niter = Kd / BK;
    for (int it = 0; it < niter; it++) {
        if (it + 1 < niter) {
            int k0 = (it + 1) * BK;
            if (A_BF16) {
                const __nv_bfloat16* A = (const __nv_bfloat16*)Av;
#pragma unroll
                for (int i = 0; i < 2; i++) {
                    int idx = t + i * 256;
                    int row = idx >> 2, c4 = idx & 3;
                    int grow = bm + row;
                    arb[i] = (grow < M)
                           ? *reinterpret_cast<const uint4*>(A + (size_t)grow * Kd + k0 + c4 * 8)
                           : make_uint4(0u, 0u, 0u, 0u);
                }
            } else {
                const float* A = (const float*)Av;
#pragma unroll
                for (int i = 0; i < 4; i++) {
                    int f4 = t + i * 256;
                    int row = f4 >> 3, c4 = f4 & 7;
                    int grow = bm + row;
                    arf[i] = (grow < M)
                           ? *reinterpret_cast<const float4*>(A + (size_t)grow * Kd + k0 + c4 * 4)
                           : make_float4(0.f, 0.f, 0.f, 0.f);
                }
            }
            loadB((it + 1) * (BK / 2));
        }
#pragma unroll
        for (int ks = 0; ks < 2; ks++) {
            int kb = ks * 8;
            unsigned ah[2][4];
#pragma unroll
            for (int mt = 0; mt < 2; mt++) {
                int base = (wm + mt * 16 + r0) * AST + kb + p;
                ah[mt][0] = As[base];
                ah[mt][1] = As[base + 8 * AST];
                ah[mt][2] = As[base + 4];
                ah[mt][3] = As[base + 8 * AST + 4];
            }
            unsigned bh[4][2];
#pragma unroll
            for (int nt = 0; nt < 4; nt++) {
                int base = (wn + nt * 8 + r0) * BST + kb + p;
                bh[nt][0] = Bs[base];
                bh[nt][1] = Bs[base + 4];
            }
#pragma unroll
            for (int mt = 0; mt < 2; mt++)
#pragma unroll
                for (int nt = 0; nt < 4; nt++)
                    mma_bf16(acc[mt][nt], ah[mt], bh[nt]);
        }
        __syncthreads();
        if (it + 1 < niter) {
            if (A_BF16) {
#pragma unroll
                for (int i = 0; i < 2; i++) {
                    int idx = t + i * 256;
                    int row = idx >> 2, c4 = idx & 3;
                    unsigned* dst = &As[row * AST + c4 * 4];
                    dst[0] = arb[i].x; dst[1] = arb[i].y; dst[2] = arb[i].z; dst[3] = arb[i].w;
                }
            } else {
#pragma unroll
                for (int i = 0; i < 4; i++) {
                    int f4 = t + i * 256;
                    int row = f4 >> 3, c4 = f4 & 7;
                    As[row * AST + c4 * 2]     = pack_bf2(arf[i].x, arf[i].y);
                    As[row * AST + c4 * 2 + 1] = pack_bf2(arf[i].z, arf[i].w);
                }
            }
            storeB();
            __syncthreads();
        }
    }

    // epilogue (+ optional fused attention partials)
    float sA[2] = {0.f, 0.f}, dA[2] = {0.f, 0.f};
    float sB[2] = {0.f, 0.f}, dB[2] = {0.f, 0.f};
    const float* attsh = FUSE_ATTN ? atts + (bn >> 6) * 64 : nullptr;
    const float* attdh = FUSE_ATTN ? attd + (bn >> 6) * 64 : nullptr;
#pragma unroll
    for (int mt = 0; mt < 2; mt++) {
#pragma unroll
        for (int nt = 0; nt < 4; nt++) {
            int grow0 = bm + wm + mt * 16 + r0;
            int gcol = bn + wn + nt * 8 + 2 * p;
            float b0v = 0.f, b1v = 0.f;
            if (ADD_BIAS) { b0v = bias[gcol]; b1v = bias[gcol + 1]; }
            float* c = acc[mt][nt];
            if (FUSE_ATTN) {
                int cih = wn + nt * 8 + 2 * p;
                float a0 = attsh[cih], a1 = attsh[cih + 1];
                float t0 = attdh[cih], t1 = attdh[cih + 1];
                sA[mt] += c[0] * a0 + c[1] * a1;
                dA[mt] += c[0] * t0 + c[1] * t1;
                sB[mt] += c[2] * a0 + c[3] * a1;
                dB[mt] += c[2] * t0 + c[3] * t1;
            }
            if (OUT_BF16) {
                __nv_bfloat162* Cb = (__nv_bfloat162*)Cv;
                if (grow0 < M)
                    Cb[((size_t)grow0 * Nd + gcol) >> 1] = __floats2bfloat162_rn(c[0] + b0v, c[1] + b1v);
                if (grow0 + 8 < M)
                    Cb[((size_t)(grow0 + 8) * Nd + gcol) >> 1] = __floats2bfloat162_rn(c[2] + b0v, c[3] + b1v);
            } else {
                float* C = (float*)Cv;
                if (grow0 < M) {
                    C[(size_t)grow0 * Nd + gcol]     = c[0] + b0v;
                    C[(size_t)grow0 * Nd + gcol + 1] = c[1] + b1v;
                }
                if (grow0 + 8 < M) {
                    C[(size_t)(grow0 + 8) * Nd + gcol]     = c[2] + b0v;
                    C[(size_t)(grow0 + 8) * Nd + gcol + 1] = c[3] + b1v;
                }
            }
        }
    }
    if (FUSE_ATTN) {
        int head = bn >> 6;
#pragma unroll
        for (int mt = 0; mt < 2; mt++) {
            sA[mt] += __shfl_xor_sync(0xffffffffu, sA[mt], 1); sA[mt] += __shfl_xor_sync(0xffffffffu, sA[mt], 2);
            dA[mt] += __shfl_xor_sync(0xffffffffu, dA[mt], 1); dA[mt] += __shfl_xor_sync(0xffffffffu, dA[mt], 2);
            sB[mt] += __shfl_xor_sync(0xffffffffu, sB[mt], 1); sB[mt] += __shfl_xor_sync(0xffffffffu, sB[mt], 2);
            dB[mt] += __shfl_xor_sync(0xffffffffu, dB[mt], 1); dB[mt] += __shfl_xor_sync(0xffffffffu, dB[mt], 2);
        }
        float* s_rs = reinterpret_cast<float*>(As);   // [BM]
        float* s_rd = s_rs + BM;                      // [BM]
        __syncthreads();
        if ((wid & 1) == 0 && p == 0) {
#pragma unroll
            for (int mt = 0; mt < 2; mt++) {
                int r = wm + mt * 16 + r0;
                s_rs[r] = sA[mt];     s_rd[r] = dA[mt];
                s_rs[r + 8] = sB[mt]; s_rd[r + 8] = dB[mt];
            }
        }
        __syncthreads();
        if ((wid & 1) == 1 && p == 0) {
#pragma unroll
            for (int mt = 0; mt < 2; mt++) {
                int r = wm + mt * 16 + r0;
                int gr = bm + r;
                if (gr < M) {
                    as_out[(size_t)gr * hstride + head] = s_rs[r] + sA[mt];
                    ad_out[(size_t)gr * hstride + head] = s_rd[r] + dA[mt];
                }
                if (gr + 8 < M) {
                    as_out[(size_t)(gr + 8) * hstride + head] = s_rs[r + 8] + sB[mt];
                    ad_out[(size_t)(gr + 8) * hstride + head] = s_rd[r + 8] + dB[mt];
                }
            }
        }
    }
}

// ---------------- 4-head aggregation: block(64) per node, 8-wide gather unroll ----------------
__device__ __forceinline__ void acc_edge(float4& acc, float e, uint2 u) {
    float2 a = __bfloat1622float2(*reinterpret_cast<__nv_bfloat162*>(&u.x));
    float2 b = __bfloat1622float2(*reinterpret_cast<__nv_bfloat162*>(&u.y));
    acc.x += e * a.x; acc.y += e * a.y;
    acc.z += e * b.x; acc.w += e * b.y;
}

__global__ __launch_bounds__(64) void agg4_kernel(
    const __nv_bfloat16* __restrict__ hw,
    const float* __restrict__ asv, const float* __restrict__ adv,
    const float* __restrict__ bias, __nv_bfloat16* __restrict__ out)
{
    int node = blockIdx.x;
    int tid = threadIdx.x;
    int start = g_rowptr[node];
    int deg = g_rowptr[node + 1] - start;

    __shared__ int   s_src[CAP];
    __shared__ float s_e[4][CAP];
    __shared__ float s_scale[4], s_m[4], s_adv[4];

    int w = tid >> 5, lane = tid & 31;
    int h3 = tid >> 4;
    float4 acc = make_float4(0.f, 0.f, 0.f, 0.f);
    const uint2* hw8 = reinterpret_cast<const uint2*>(hw);

    if (deg <= CAP) {
        for (int i = tid; i < deg; i += 64) s_src[i] = g_csrc[start + i];
        __syncthreads();
        for (int h = w; h < 4; h += 2) {
            float adh = adv[node * 4 + h];
            float mx = -1e30f;
            for (int i = lane; i < deg; i += 32) {
                float e = asv[s_src[i] * 4 + h] + adh;
                e = e >= 0.f ? e : 0.2f * e;
                s_e[h][i] = e;
                mx = fmaxf(mx, e);
            }
#pragma unroll
            for (int o = 16; o; o >>= 1) mx = fmaxf(mx, __shfl_xor_sync(0xffffffffu, mx, o));
            float den = 0.f;
            for (int i = lane; i < deg; i += 32) {
                float ex = __expf(s_e[h][i] - mx);
                s_e[h][i] = ex;
                den += ex;
            }
#pragma unroll
            for (int o = 16; o; o >>= 1) den += __shfl_xor_sync(0xffffffffu, den, o);
            if (lane == 0) s_scale[h] = 1.f / (den + 1e-16f);
        }
        __syncthreads();
        const float* eh = s_e[h3];
        int i = 0;
        for (; i + 8 <= deg; i += 8) {
            int   s0 = s_src[i],     s1 = s_src[i + 1], s2 = s_src[i + 2], s3 = s_src[i + 3];
            int   s4 = s_src[i + 4], s5 = s_src[i + 5], s6 = s_src[i + 6], s7 = s_src[i + 7];
            float e0 = eh[i],     e1 = eh[i + 1], e2 = eh[i + 2], e3 = eh[i + 3];
            float e4 = eh[i + 4], e5 = eh[i + 5], e6 = eh[i + 6], e7 = eh[i + 7];
            uint2 u0 = hw8[(size_t)s0 * 64 + tid];
            uint2 u1 = hw8[(size_t)s1 * 64 + tid];
            uint2 u2 = hw8[(size_t)s2 * 64 + tid];
            uint2 u3 = hw8[(size_t)s3 * 64 + tid];
            uint2 u4 = hw8[(size_t)s4 * 64 + tid];
            uint2 u5 = hw8[(size_t)s5 * 64 + tid];
            uint2 u6 = hw8[(size_t)s6 * 64 + tid];
            uint2 u7 = hw8[(size_t)s7 * 64 + tid];
            acc_edge(acc, e0, u0); acc_edge(acc, e1, u1);
            acc_edge(acc, e2, u2); acc_edge(acc, e3, u3);
            acc_edge(acc, e4, u4); acc_edge(acc, e5, u5);
            acc_edge(acc, e6, u6); acc_edge(acc, e7, u7);
        }
        for (; i + 4 <= deg; i += 4) {
            int s0 = s_src[i], s1 = s_src[i + 1], s2 = s_src[i + 2], s3 = s_src[i + 3];
            float e0 = eh[i], e1 = eh[i + 1], e2 = eh[i + 2], e3 = eh[i + 3];
            uint2 u0 = hw8[(size_t)s0 * 64 + tid];
            uint2 u1 = hw8[(size_t)s1 * 64 + tid];
            uint2 u2 = hw8[(size_t)s2 * 64 + tid];
            uint2 u3 = hw8[(size_t)s3 * 64 + tid];
            acc_edge(acc, e0, u0); acc_edge(acc, e1, u1);
            acc_edge(acc, e2, u2); acc_edge(acc, e3, u3);
        }
        for (; i < deg; i++) {
            uint2 u0 = hw8[(size_t)s_src[i] * 64 + tid];
            acc_edge(acc, eh[i], u0);
        }
    } else {
        for (int h = w; h < 4; h += 2) {
            float adh = adv[node * 4 + h];
            float mx = -1e30f;
            for (int i = lane; i < deg; i += 32) {
                float e = asv[g_csrc[start + i] * 4 + h] + adh;
                e = e >= 0.f ? e : 0.2f * e;
                mx = fmaxf(mx, e);
            }
#pragma unroll
            for (int o = 16; o; o >>= 1) mx = fmaxf(mx, __shfl_xor_sync(0xffffffffu, mx, o));
            float den = 0.f;
            for (int i = lane; i < deg; i += 32) {
                float e = asv[g_csrc[start + i] * 4 + h] + adh;
                e = e >= 0.f ? e : 0.2f * e;
                den += __expf(e - mx);
            }
#pragma unroll
            for (int o = 16; o; o >>= 1) den += __shfl_xor_sync(0xffffffffu, den, o);
            if (lane == 0) {
                s_m[h] = mx;
                s_scale[h] = 1.f / (den + 1e-16f);
                s_adv[h] = adh;
            }
        }
        __syncthreads();
        float mxh = s_m[h3], adh = s_adv[h3];
        for (int i = 0; i < deg; i++) {
            int s = g_csrc[start + i];
            float e = asv[s * 4 + h3] + adh;
            e = e >= 0.f ? e : 0.2f * e;
            float ex = __expf(e - mxh);
            uint2 u0 = hw8[(size_t)s * 64 + tid];
            acc_edge(acc, ex, u0);
        }
    }

    float sc = s_scale[h3];
    float4 b = reinterpret_cast<const float4*>(bias)[tid];
    acc.x = acc.x * sc + b.x;
    acc.y = acc.y * sc + b.y;
    acc.z = acc.z * sc + b.z;
    acc.w = acc.w * sc + b.w;
    acc.x = acc.x > 0.f ? acc.x : (__expf(acc.x) - 1.f);
    acc.y = acc.y > 0.f ? acc.y : (__expf(acc.y) - 1.f);
    acc.z = acc.z > 0.f ? acc.z : (__expf(acc.z) - 1.f);
    acc.w = acc.w > 0.f ? acc.w : (__expf(acc.w) - 1.f);
    __nv_bfloat162 p0 = __floats2bfloat162_rn(acc.x, acc.y);
    __nv_bfloat162 p1 = __floats2bfloat162_rn(acc.z, acc.w);
    uint2 o;
    o.x = *reinterpret_cast<unsigned*>(&p0);
    o.y = *reinterpret_cast<unsigned*>(&p1);
    reinterpret_cast<uint2*>(out)[(size_t)node * 64 + tid] = o;
}

// ---------------- 1-head aggregation: warp per node, bf162 gather, fp32 out ----------------
__global__ __launch_bounds__(64) void agg1_kernel(
    const __nv_bfloat16* __restrict__ hw,
    const float* __restrict__ asv, const float* __restrict__ adv,
    const float* __restrict__ bias, float* __restrict__ out)
{
    __shared__ int   s_src[2][CAP];
    __shared__ float s_e[2][CAP];
    int w = threadIdx.x >> 5, lane = threadIdx.x & 31;
    int node = blockIdx.x * 2 + w;
    if (node >= NNODES) return;
    int start = g_rowptr[node];
    int deg = g_rowptr[node + 1] - start;
    float adh = adv[node];

    float acc_x = 0.f, acc_y = 0.f;
    float den;
    const __nv_bfloat162* hw2 = reinterpret_cast<const __nv_bfloat162*>(hw);

    if (deg <= CAP) {
        float mx = -1e30f;
        for (int i = lane; i < deg; i += 32) {
            int s = g_csrc[start + i];
            s_src[w][i] = s;
            float e = asv[s] + adh;
            e = e >= 0.f ? e : 0.2f * e;
            s_e[w][i] = e;
            mx = fmaxf(mx, e);
        }
#pragma unroll
        for (int o = 16; o; o >>= 1) mx = fmaxf(mx, __shfl_xor_sync(0xffffffffu, mx, o));
        __syncwarp();
        den = 0.f;
        for (int i = lane; i < deg; i += 32) {
            float ex = __expf(s_e[w][i] - mx);
            s_e[w][i] = ex;
            den += ex;
        }
#pragma unroll
        for (int o = 16; o; o >>= 1) den += __shfl_xor_sync(0xffffffffu, den, o);
        __syncwarp();
        int i = 0;
        for (; i + 4 <= deg; i += 4) {
            int s0 = s_src[w][i], s1 = s_src[w][i + 1], s2 = s_src[w][i + 2], s3 = s_src[w][i + 3];
            float e0 = s_e[w][i], e1 = s_e[w][i + 1], e2 = s_e[w][i + 2], e3 = s_e[w][i + 3];
            float2 v0 = __bfloat1622float2(hw2[(size_t)s0 * 32 + lane]);
            float2 v1 = __bfloat1622float2(hw2[(size_t)s1 * 32 + lane]);
            float2 v2 = __bfloat1622float2(hw2[(size_t)s2 * 32 + lane]);
            float2 v3 = __bfloat1622float2(hw2[(size_t)s3 * 32 + lane]);
            acc_x += e0 * v0.x + e1 * v1.x + e2 * v2.x + e3 * v3.x;
            acc_y += e0 * v0.y + e1 * v1.y + e2 * v2.y + e3 * v3.y;
        }
        for (; i < deg; i++) {
            float e0 = s_e[w][i];
            float2 v0 = __bfloat1622float2(hw2[(size_t)s_src[w][i] * 32 + lane]);
            acc_x += e0 * v0.x; acc_y += e0 * v0.y;
        }
    } else {
        float mx = -1e30f;
        for (int i = lane; i < deg; i += 32) {
            float e = asv[g_csrc[start + i]] + adh;
            e = e >= 0.f ? e : 0.2f * e;
            mx = fmaxf(mx, e);
        }
#pragma unroll
        for (int o = 16; o; o >>= 1) mx = fmaxf(mx, __shfl_xor_sync(0xffffffffu, mx, o));
        den = 0.f;
        for (int i = lane; i < deg; i += 32) {
            float e = asv[g_csrc[start + i]] + adh;
            e = e >= 0.f ? e : 0.2f * e;
            den += __expf(e - mx);
        }
#pragma unroll
        for (int o = 16; o; o >>= 1) den += __shfl_xor_sync(0xffffffffu, den, o);
        for (int i = 0; i < deg; i++) {
            int s = g_csrc[start + i];
            float e = asv[s] + adh;
            e = e >= 0.f ? e : 0.2f * e;
            float ex = __expf(e - mx);
            float2 v0 = __bfloat1622float2(hw2[(size_t)s * 32 + lane]);
            acc_x += ex * v0.x; acc_y += ex * v0.y;
        }
    }
    float sc = 1.f / (den + 1e-16f);
    float2 b = reinterpret_cast<const float2*>(bias)[lane];
    float2 r;
    r.x = acc_x * sc + b.x;
    r.y = acc_y * sc + b.y;
    reinterpret_cast<float2*>(out)[(size_t)node * 32 + lane] = r;
}

// ---------------- global mean pool (two-stage, batch is sorted) ----------------
__global__ void pool_kernel(const int* __restrict__ batch) {
    __shared__ float sacc[NGRAPH * 64];
    __shared__ float scnt[NGRAPH];
    int t = threadIdx.x;  // 64 threads
    for (int i = t; i < NGRAPH * 64; i += 64) sacc[i] = 0.f;
    if (t < NGRAPH) scnt[t] = 0.f;
    __syncthreads();
    int n0 = blockIdx.x * 256;
    int n1 = min(n0 + 256, NNODES);
    int bmin = NGRAPH, bmax = -1;
    for (int n = n0; n < n1; n++) {
        int b = batch[n];
        sacc[b * 64 + t] += g_h3[(size_t)n * 64 + t];
        if (t == 0) scnt[b] += 1.f;
        bmin = min(bmin, b); bmax = max(bmax, b);
    }
    __syncthreads();
    for (int b = bmin; b <= bmax; b++) {
        atomicAdd(&g_pool[b * 64 + t], sacc[b * 64 + t]);
        if (t == 0) atomicAdd(&g_pool[NGRAPH * 64 + b], scnt[b]);
    }
}

// ---------------- decoder ----------------
__global__ void decoder_kernel(
    const float* __restrict__ gf, const float* __restrict__ Wg, const float* __restrict__ bg,
    const float* __restrict__ Wd1, const float* __restrict__ bd1,
    const float* __restrict__ gamma, const float* __restrict__ beta,
    const float* __restrict__ Wd2, const float* __restrict__ bd2,
    float* __restrict__ out)
{
    __shared__ float z[NGRAPH][128];
    __shared__ float z2[NGRAPH][64];
    __shared__ float logits[NGRAPH][256];
    int t = threadIdx.x;  // 256
    for (int idx = t; idx < NGRAPH * 64; idx += 256) {
        int g = idx / 64, c = idx % 64;
        float cnt = g_pool[NGRAPH * 64 + g];
        z[g][c] = g_pool[idx] / fmaxf(cnt, 1.0f);
        float s = bg[c];
        for (int k = 0; k < 4; k++) s += gf[g * 4 + k] * Wg[k * 64 + c];
        z[g][64 + c] = fmaxf(s, 0.f);
    }
    __syncthreads();
    for (int idx = t; idx < NGRAPH * 64; idx += 256) {
        int g = idx / 64, c = idx % 64;
        float s = bd1[c];
        for (int k = 0; k < 128; k++) s += z[g][k] * Wd1[k * 64 + c];
        s = s * gamma[c] + beta[c];
        z2[g][c] = fmaxf(s, 0.f);
    }
    __syncthreads();
    for (int idx = t; idx < NGRAPH * 256; idx += 256) {
        int g = idx / 256, o = idx % 256;
        float s = bd2[o];
        for (int k = 0; k < 64; k++) s += z2[g][k] * Wd2[k * 256 + o];
        logits[g][o] = s;
    }
    __syncthreads();
    int warp = t >> 5, lane = t & 31;
    for (int g = warp; g < NGRAPH; g += 8) {
        float m = -1e30f;
        for (int o = lane; o < 256; o += 32) m = fmaxf(m, logits[g][o]);
#pragma unroll
        for (int off = 16; off; off >>= 1) m = fmaxf(m, __shfl_xor_sync(0xffffffffu, m, off));
        float s = 0.f;
        for (int o = lane; o < 256; o += 32) s += __expf(logits[g][o] - m);
#pragma unroll
        for (int off = 16; off; off >>= 1) s += __shfl_xor_sync(0xffffffffu, s, off);
        float inv = 1.f / s;
        for (int o = lane; o < 256; o += 32) out[g * 256 + o] = __expf(logits[g][o] - m) * inv;
    }
}

// ---------------- launch ----------------
extern "C" void kernel_launch(void* const* d_in, const int* in_sizes, int n_in,
                              void* d_out, int out_size)
{
    const float* x    = (const float*)d_in[0];
    const int*   ei   = (const int*)d_in[1];
    const int*   batch = (const int*)d_in[2];
    const float* gf   = (const float*)d_in[3];
    const float* W_enc = (const float*)d_in[4];
    const float* b_enc = (const float*)d_in[5];
    const float* W1  = (const float*)d_in[6];
    const float* as1 = (const float*)d_in[7];
    const float* ad1 = (const float*)d_in[8];
    const float* b1  = (const float*)d_in[9];
    const float* W2  = (const float*)d_in[10];
    const float* as2 = (const float*)d_in[11];
    const float* ad2 = (const float*)d_in[12];
    const float* b2  = (const float*)d_in[13];
    const float* W3  = (const float*)d_in[14];
    const float* as3 = (const float*)d_in[15];
    const float* ad3 = (const float*)d_in[16];
    const float* b3  = (const float*)d_in[17];
    const float* Wg  = (const float*)d_in[18];
    const float* bg  = (const float*)d_in[19];
    const float* Wd1 = (const float*)d_in[20];
    const float* bd1 = (const float*)d_in[21];
    const float* gamma = (const float*)d_in[22];
    const float* beta  = (const float*)d_in[23];
    const float* Wd2 = (const float*)d_in[24];
    const float* bd2 = (const float*)d_in[25];
    float* out = (float*)d_out;

    void *p;
    cudaGetSymbolAddress(&p, g_h0);   __nv_bfloat16* h0   = (__nv_bfloat16*)p;
    cudaGetSymbolAddress(&p, g_bufA); __nv_bfloat16* bufA = (__nv_bfloat16*)p;
    cudaGetSymbolAddress(&p, g_bufB); __nv_bfloat16* bufB = (__nv_bfloat16*)p;
    cudaGetSymbolAddress(&p, g_h3);   float* h3  = (float*)p;
    cudaGetSymbolAddress(&p, g_asA);  float* asA = (float*)p;
    cudaGetSymbolAddress(&p, g_adA);  float* adA = (float*)p;
    cudaGetSymbolAddress(&p, g_Wp);   unsigned* Wp = (unsigned*)p;
    float* as_s0 = asA;                  float* ad_s0 = adA;
    float* as_s1 = asA + NNODES * 4;     float* ad_s1 = adA + NNODES * 4;
    float* as_s2 = asA + 2 * NNODES * 4; float* ad_s2 = adA + 2 * NNODES * 4;

    static bool attr_done = false;
    if (!attr_done) {
        cudaFuncSetAttribute(scan_kernel, cudaFuncAttributeMaxDynamicSharedMemorySize,
                             NNODES * (int)sizeof(int));
        attr_done = true;
    }

    // setup + weight packing (main stream)
    zero_setup_kernel<<<(NNODES + 255) / 256, 256>>>();
    packW_all_kernel<<<(WP_TOT + 255) / 256, 256>>>(W_enc, W1, W2, W3);

    // fork: CSR build on side stream, GEMMs on main stream
    cudaEventRecord(g_sb.ev_fork, 0);
    cudaStreamWaitEvent(g_sb.s2, g_sb.ev_fork, 0);
    deg_kernel<<<(ETOT + 255) / 256, 256, 0, g_sb.s2>>>(ei);
    scan_kernel<<<1, 1024, NNODES * sizeof(int), g_sb.s2>>>();
    fill_kernel<<<(ETOT + 255) / 256, 256, 0, g_sb.s2>>>(ei);
    cudaEventRecord(g_sb.ev_join, g_sb.s2);

    dim3 blk(256);
    int mg = (NNODES + BM - 1) / BM;
    // encoder: h0(bf16) = x @ W_enc + b_enc   (fp32 A path)
    gemm_kernel<true, true, false, false><<<dim3(1, mg), blk>>>(
        x, Wp + OFF_ENC, b_enc, h0, NNODES, 32, 64, nullptr, nullptr, nullptr, nullptr, 0);

    // conv1 GEMM (bf16 A) + fused attention
    gemm_kernel<false, true, true, true><<<dim3(4, mg), blk>>>(
        h0, Wp + OFF_W1, nullptr, bufB, NNODES, 64, 256, as1, ad1, as_s0, ad_s0, 4);

    // join CSR before aggregation
    cudaStreamWaitEvent(0, g_sb.ev_join, 0);
    agg4_kernel<<<NNODES, 64>>>(bufB, as_s0, ad_s0, b1, bufA);

    // conv2
    gemm_kernel<false, true, true, true><<<dim3(4, mg), blk>>>(
        bufA, Wp + OFF_W2, nullptr, bufB, NNODES, 256, 256, as2, ad2, as_s1, ad_s1, 4);
    agg4_kernel<<<NNODES, 64>>>(bufB, as_s1, ad_s1, b2, bufA);

    // conv3
    gemm_kernel<false, true, true, true><<<dim3(1, mg), blk>>>(
        bufA, Wp + OFF_W3, nullptr, bufB, NNODES, 256, 64, as3, ad3, as_s2, ad_s2, 1);
    agg1_kernel<<<(NNODES + 1) / 2, 64>>>(bufB, as_s2, ad_s2, b3, h3);

    // pooling + decoder (two-stage; low-contention atomics)
    pool_kernel<<<(NNODES + 255) / 256, 64>>>(batch);
    decoder_kernel<<<1, 256>>>(gf, Wg, bg, Wd1, bd1, gamma, beta, Wd2, bd2, out);
}